// round 2
// baseline (speedup 1.0000x reference)
#include <cuda_runtime.h>
#include <cstdint>

#define N_NODES 50000
#define D 128
#define D_OUT 64
#define BN_EPS 1e-5f

// ---------------- scratch (device globals; no allocation allowed) ----------
__device__ float g_agg[(size_t)N_NODES * D];
__device__ float g_h0[(size_t)N_NODES * D];
__device__ float g_h1[(size_t)N_NODES * D];
__device__ float g_cnt[N_NODES];
__device__ float g_inv[N_NODES];
__device__ float g_colsum[D];
__device__ float g_colsq[D];
__device__ float g_scale[D];
__device__ float g_shift[D];

// ---------------- helpers ---------------------------------------------------
__device__ __forceinline__ void red_add_v4(float* addr, float4 v) {
    asm volatile("red.global.add.v4.f32 [%0], {%1, %2, %3, %4};"
                 :: "l"(addr), "f"(v.x), "f"(v.y), "f"(v.z), "f"(v.w)
                 : "memory");
}

// zero a float buffer (n multiple of 4)
__global__ void k_zero(float* __restrict__ p, int n4) {
    int i = blockIdx.x * blockDim.x + threadIdx.x;
    float4 z = make_float4(0.f, 0.f, 0.f, 0.f);
    for (; i < n4; i += gridDim.x * blockDim.x)
        reinterpret_cast<float4*>(p)[i] = z;
}

// ---------------- scatter-add aggregation (warp per edge) ------------------
template <bool COUNT>
__global__ void k_scatter(const float* __restrict__ xin,
                          const int* __restrict__ src,
                          const int* __restrict__ dst,
                          float* __restrict__ agg, int E) {
    int e = blockIdx.x * 8 + (threadIdx.x >> 5);
    if (e >= E) return;
    int lane = threadIdx.x & 31;
    int s = src[e];
    int d = dst[e];
    float4 v = __ldg(reinterpret_cast<const float4*>(xin + (size_t)s * D) + lane);
    red_add_v4(agg + (size_t)d * D + lane * 4, v);
    if (COUNT && lane == 0) atomicAdd(&g_cnt[d], 1.0f);
}

__global__ void k_inv(int n) {
    int i = blockIdx.x * blockDim.x + threadIdx.x;
    if (i < n) g_inv[i] = 1.0f / fmaxf(g_cnt[i], 1.0f);
}

// ---------------- fused SAGE GEMM: out = (agg*inv)@Wl + x@Wr + b ------------
// single GEMM with K = 256 (first 128 from agg*inv via Wl, next 128 from x via Wr)
// BM=128, BK=32, BN template (128 or 64); 256 threads, 8x(BN/16) microtile.
template <int BN>
__global__ __launch_bounds__(256)
void k_sage_gemm(const float* __restrict__ agg, const float* __restrict__ inv,
                 const float* __restrict__ xin,
                 const float* __restrict__ Wl, const float* __restrict__ Wr,
                 const float* __restrict__ bias, float* __restrict__ out) {
    constexpr int BM = 128;
    constexpr int BK = 32;
    constexpr int TM = 8;
    constexpr int TN = BN / 16;

    __shared__ float As[BK][BM + 4];
    __shared__ float Ws[BK][BN];

    const int tid = threadIdx.x;
    const int tx = tid & 15;        // col group
    const int ty = tid >> 4;        // row group
    const int rowBase = blockIdx.x * BM;

    float acc[TM][TN];
#pragma unroll
    for (int i = 0; i < TM; i++)
#pragma unroll
        for (int j = 0; j < TN; j++) acc[i][j] = 0.f;

    for (int kt = 0; kt < 256 / BK; kt++) {
        const int kk0 = kt * BK;                // combined-K base, all 32 in one half
        const bool firstHalf = (kk0 < 128);
        const int kcol = firstHalf ? kk0 : kk0 - 128;
        const float* Asrc = firstHalf ? agg : xin;

        // load A tile: BM x BK = 4096 floats = 1024 float4, 4 per thread
#pragma unroll
        for (int t = 0; t < 4; t++) {
            int lin = tid + t * 256;            // 0..1023
            int m = lin >> 3;                   // 8 float4 per row
            int k4 = lin & 7;
            int row = rowBase + m;
            float4 v = make_float4(0.f, 0.f, 0.f, 0.f);
            if (row < N_NODES) {
                v = __ldg(reinterpret_cast<const float4*>(Asrc + (size_t)row * D + kcol) + k4);
                if (firstHalf) {
                    float s = __ldg(inv + row);
                    v.x *= s; v.y *= s; v.z *= s; v.w *= s;
                }
            }
            As[k4 * 4 + 0][m] = v.x;
            As[k4 * 4 + 1][m] = v.y;
            As[k4 * 4 + 2][m] = v.z;
            As[k4 * 4 + 3][m] = v.w;
        }

        // load W tile: BK x BN floats
        constexpr int W4 = BK * BN / 4;         // 1024 (BN=128) or 512 (BN=64)
#pragma unroll
        for (int t = 0; t < W4 / 256; t++) {
            int lin = tid + t * 256;
            int k = lin / (BN / 4);
            int n4 = lin % (BN / 4);
            int kk = kk0 + k;
            const float* Wp = (kk < 128) ? (Wl + (size_t)kk * BN)
                                         : (Wr + (size_t)(kk - 128) * BN);
            float4 w = __ldg(reinterpret_cast<const float4*>(Wp) + n4);
            *reinterpret_cast<float4*>(&Ws[k][n4 * 4]) = w;
        }
        __syncthreads();

#pragma unroll
        for (int k = 0; k < BK; k++) {
            float a[TM], w[TN];
#pragma unroll
            for (int i = 0; i < TM; i++) a[i] = As[k][ty + i * 16];
#pragma unroll
            for (int j = 0; j < TN; j++) w[j] = Ws[k][tx + j * 16];
#pragma unroll
            for (int i = 0; i < TM; i++)
#pragma unroll
                for (int j = 0; j < TN; j++)
                    acc[i][j] = fmaf(a[i], w[j], acc[i][j]);
        }
        __syncthreads();
    }

    // epilogue: add bias, store
#pragma unroll
    for (int j = 0; j < TN; j++) {
        int col = tx + j * 16;
        float b = __ldg(bias + col);
#pragma unroll
        for (int i = 0; i < TM; i++) {
            int row = rowBase + ty + i * 16;
            if (row < N_NODES)
                out[(size_t)row * BN + col] = acc[i][j] + b;
        }
    }
}

// ---------------- batch norm ------------------------------------------------
__global__ void k_bn_stats(const float* __restrict__ h, int n) {
    int col = threadIdx.x;      // blockDim = 128
    float s = 0.f, q = 0.f;
    for (int r = blockIdx.x; r < n; r += gridDim.x) {
        float v = h[(size_t)r * D + col];
        s += v;
        q += v * v;
    }
    atomicAdd(&g_colsum[col], s);
    atomicAdd(&g_colsq[col], q);
}

__global__ void k_bn_finalize(const float* __restrict__ gamma,
                              const float* __restrict__ beta) {
    int c = threadIdx.x;        // 128 threads, 1 block
    float mu = g_colsum[c] / (float)N_NODES;
    float var = g_colsq[c] / (float)N_NODES - mu * mu;
    float sc = gamma[c] * rsqrtf(var + BN_EPS);
    g_scale[c] = sc;
    g_shift[c] = beta[c] - mu * sc;
}

__global__ void k_bn_apply_relu(float* __restrict__ h, int total) {
    int i = blockIdx.x * blockDim.x + threadIdx.x;
    for (; i < total; i += gridDim.x * blockDim.x) {
        int c = i & (D - 1);
        float v = h[i] * g_scale[c] + g_shift[c];
        h[i] = fmaxf(v, 0.f);
    }
}

// ---------------- log-softmax over 64 cols (warp per row) ------------------
__global__ void k_logsoftmax(float* __restrict__ out, int n) {
    int row = blockIdx.x * 8 + (threadIdx.x >> 5);
    if (row >= n) return;
    int lane = threadIdx.x & 31;
    float* p = out + (size_t)row * D_OUT;
    float a = p[lane];
    float b = p[lane + 32];
    float m = fmaxf(a, b);
#pragma unroll
    for (int o = 16; o > 0; o >>= 1) m = fmaxf(m, __shfl_xor_sync(0xffffffffu, m, o));
    float e = expf(a - m) + expf(b - m);
#pragma unroll
    for (int o = 16; o > 0; o >>= 1) e += __shfl_xor_sync(0xffffffffu, e, o);
    float l = m + logf(e);
    p[lane] = a - l;
    p[lane + 32] = b - l;
}

// ---------------- launch ----------------------------------------------------
extern "C" void kernel_launch(void* const* d_in, const int* in_sizes, int n_in,
                              void* d_out, int out_size) {
    const float* x   = (const float*)d_in[0];
    const int* ei    = (const int*)d_in[1];
    const float* Wl0 = (const float*)d_in[2];
    const float* Wr0 = (const float*)d_in[3];
    const float* b0  = (const float*)d_in[4];
    const float* g0  = (const float*)d_in[5];
    const float* be0 = (const float*)d_in[6];
    const float* Wl1 = (const float*)d_in[7];
    const float* Wr1 = (const float*)d_in[8];
    const float* b1  = (const float*)d_in[9];
    const float* g1  = (const float*)d_in[10];
    const float* be1 = (const float*)d_in[11];
    const float* Wl2 = (const float*)d_in[12];
    const float* Wr2 = (const float*)d_in[13];
    const float* b2  = (const float*)d_in[14];
    float* out = (float*)d_out;

    const int E = in_sizes[1] / 2;
    const int* src = ei;
    const int* dst = ei + E;

    float *agg, *h0, *h1, *cnt, *inv, *colsum, *colsq;
    cudaGetSymbolAddress((void**)&agg, g_agg);
    cudaGetSymbolAddress((void**)&h0, g_h0);
    cudaGetSymbolAddress((void**)&h1, g_h1);
    cudaGetSymbolAddress((void**)&cnt, g_cnt);
    cudaGetSymbolAddress((void**)&inv, g_inv);
    cudaGetSymbolAddress((void**)&colsum, g_colsum);
    cudaGetSymbolAddress((void**)&colsq, g_colsq);

    const int scatterBlocks = (E + 7) / 8;
    const int gemmBlocks = (N_NODES + 127) / 128;
    const int ND4 = N_NODES * D / 4;

    // ---- layer 0 ----
    k_zero<<<2048, 256>>>(agg, ND4);
    k_zero<<<64, 256>>>(cnt, N_NODES / 4);
    k_zero<<<1, 64>>>(colsum, D / 4);
    k_zero<<<1, 64>>>(colsq, D / 4);
    k_scatter<true><<<scatterBlocks, 256>>>(x, src, dst, agg, E);
    k_inv<<<(N_NODES + 255) / 256, 256>>>(N_NODES);
    k_sage_gemm<128><<<gemmBlocks, 256>>>(agg, inv, x, Wl0, Wr0, b0, h0);
    k_bn_stats<<<512, 128>>>(h0, N_NODES);
    k_bn_finalize<<<1, 128>>>(g0, be0);
    k_bn_apply_relu<<<2048, 256>>>(h0, N_NODES * D);

    // ---- layer 1 ----
    k_zero<<<2048, 256>>>(agg, ND4);
    k_zero<<<1, 64>>>(colsum, D / 4);
    k_zero<<<1, 64>>>(colsq, D / 4);
    k_scatter<false><<<scatterBlocks, 256>>>(h0, src, dst, agg, E);
    k_sage_gemm<128><<<gemmBlocks, 256>>>(agg, inv, h0, Wl1, Wr1, b1, h1);
    k_bn_stats<<<512, 128>>>(h1, N_NODES);
    k_bn_finalize<<<1, 128>>>(g1, be1);
    k_bn_apply_relu<<<2048, 256>>>(h1, N_NODES * D);

    // ---- layer 2 ----
    k_zero<<<2048, 256>>>(agg, ND4);
    k_scatter<false><<<scatterBlocks, 256>>>(h1, src, dst, agg, E);
    k_sage_gemm<64><<<gemmBlocks, 256>>>(agg, inv, h1, Wl2, Wr2, b2, out);
    k_logsoftmax<<<(N_NODES + 7) / 8, 256>>>(out, N_NODES);
}

// round 3
// speedup vs baseline: 1.4445x; 1.4445x over previous
#include <cuda_runtime.h>
#include <cstdint>

#define N_NODES 50000
#define E_MAX   800000
#define D 128
#define D_OUT 64
#define BN_EPS 1e-5f

// ---------------- scratch (device globals; no allocation allowed) ----------
__device__ float g_agg[(size_t)N_NODES * D];   // neighbor means
__device__ float g_h0[(size_t)N_NODES * D];
__device__ float g_h1[(size_t)N_NODES * D];
__device__ int   g_cnti[N_NODES];
__device__ int   g_rowptr[N_NODES + 1];
__device__ int   g_cursor[N_NODES];
__device__ int   g_csr[E_MAX];
__device__ float g_colsum[D];
__device__ float g_colsq[D];
__device__ float g_scale[D];
__device__ float g_shift[D];

// ---------------- small utils ----------------------------------------------
__global__ void k_zero_f(float* __restrict__ p, int n) {
    int i = blockIdx.x * blockDim.x + threadIdx.x;
    for (; i < n; i += gridDim.x * blockDim.x) p[i] = 0.f;
}
__global__ void k_zero_i(int* __restrict__ p, int n) {
    int i = blockIdx.x * blockDim.x + threadIdx.x;
    for (; i < n; i += gridDim.x * blockDim.x) p[i] = 0;
}

// ---------------- CSR build -------------------------------------------------
__global__ void k_hist(const int* __restrict__ dst, int E, int* __restrict__ cnt) {
    int e = blockIdx.x * blockDim.x + threadIdx.x;
    for (; e < E; e += gridDim.x * blockDim.x)
        atomicAdd(&cnt[dst[e]], 1);
}

// single block, 1024 threads: segmented exclusive scan of counts
__global__ void k_scan(const int* __restrict__ cnt, int* __restrict__ row_ptr,
                       int* __restrict__ cursor) {
    constexpr int SEG = (N_NODES + 1023) / 1024;   // 49
    int t = threadIdx.x;
    int beg = t * SEG;
    int end = min(beg + SEG, N_NODES);
    int s = 0;
    for (int i = beg; i < end; i++) s += cnt[i];
    __shared__ int sh[1024];
    sh[t] = s;
    __syncthreads();
    for (int off = 1; off < 1024; off <<= 1) {
        int v = (t >= off) ? sh[t - off] : 0;
        __syncthreads();
        sh[t] += v;
        __syncthreads();
    }
    int pos = sh[t] - s;     // exclusive prefix over segments
    for (int i = beg; i < end; i++) {
        row_ptr[i] = pos;
        cursor[i]  = pos;
        pos += cnt[i];
    }
    if (beg < N_NODES && end == N_NODES) row_ptr[N_NODES] = pos;
}

__global__ void k_fill(const int* __restrict__ src, const int* __restrict__ dst,
                       int E, int* __restrict__ cursor, int* __restrict__ csr) {
    int e = blockIdx.x * blockDim.x + threadIdx.x;
    for (; e < E; e += gridDim.x * blockDim.x) {
        int d = dst[e];
        int p = atomicAdd(&cursor[d], 1);
        csr[p] = src[e];
    }
}

// ---------------- gather aggregation: mean over neighbors ------------------
// one warp per node; lanes own 4 contiguous features (float4)
__global__ __launch_bounds__(256)
void k_aggregate(const float* __restrict__ xin, const int* __restrict__ csr,
                 const int* __restrict__ row_ptr, float* __restrict__ mean) {
    int w = (blockIdx.x * blockDim.x + threadIdx.x) >> 5;
    if (w >= N_NODES) return;
    int lane = threadIdx.x & 31;
    int beg = __ldg(row_ptr + w);
    int end = __ldg(row_ptr + w + 1);
    float4 a0 = make_float4(0.f, 0.f, 0.f, 0.f);
    float4 a1 = make_float4(0.f, 0.f, 0.f, 0.f);
    int i = beg;
    for (; i + 1 < end; i += 2) {
        int s0 = __ldg(csr + i);
        int s1 = __ldg(csr + i + 1);
        float4 v0 = __ldg(reinterpret_cast<const float4*>(xin + (size_t)s0 * D) + lane);
        float4 v1 = __ldg(reinterpret_cast<const float4*>(xin + (size_t)s1 * D) + lane);
        a0.x += v0.x; a0.y += v0.y; a0.z += v0.z; a0.w += v0.w;
        a1.x += v1.x; a1.y += v1.y; a1.z += v1.z; a1.w += v1.w;
    }
    if (i < end) {
        int s0 = __ldg(csr + i);
        float4 v0 = __ldg(reinterpret_cast<const float4*>(xin + (size_t)s0 * D) + lane);
        a0.x += v0.x; a0.y += v0.y; a0.z += v0.z; a0.w += v0.w;
    }
    float inv = 1.f / (float)max(end - beg, 1);
    float4 r = make_float4((a0.x + a1.x) * inv, (a0.y + a1.y) * inv,
                           (a0.z + a1.z) * inv, (a0.w + a1.w) * inv);
    reinterpret_cast<float4*>(mean + (size_t)w * D)[lane] = r;
}

// ---------------- fused SAGE GEMM with packed f32x2 FFMA2 -------------------
// out[N, BN] = mean @ Wl + x @ Wr + b   (combined K = 256)
// BM=128, BK=32; 256 threads = 16x16; each thread: 8 rows x (BN/16) cols
template <int BN>
__global__ __launch_bounds__(256, 2)
void k_sage_gemm(const float* __restrict__ A0, const float* __restrict__ A1,
                 const float* __restrict__ Wl, const float* __restrict__ Wr,
                 const float* __restrict__ bias, float* __restrict__ out) {
    constexpr int BM = 128;
    constexpr int BK = 32;
    constexpr int NC = BN / 64;          // float4-col-chunks per thread (2 or 1)

    __shared__ float As[BK][BM + 4];     // +4 keeps 16B alignment of rows
    __shared__ float Ws[BK][BN];

    const int tid = threadIdx.x;
    const int tx = tid & 15;
    const int ty = tid >> 4;
    const int rowBase = blockIdx.x * BM;

    unsigned long long acc[8][2 * NC];
#pragma unroll
    for (int i = 0; i < 8; i++)
#pragma unroll
        for (int j = 0; j < 2 * NC; j++) acc[i][j] = 0ull;

#pragma unroll 1
    for (int kt = 0; kt < 256 / BK; kt++) {
        const int kk0 = kt * BK;
        const float* Asrc = (kk0 < 128) ? A0 : A1;
        const int kcol = kk0 & 127;

        // A tile: BM x BK (transposed into As[k][m]); coalesced float4 loads
#pragma unroll
        for (int t = 0; t < 4; t++) {
            int lin = tid + t * 256;
            int m = lin >> 3;
            int k4 = lin & 7;
            int row = rowBase + m;
            float4 v = make_float4(0.f, 0.f, 0.f, 0.f);
            if (row < N_NODES)
                v = __ldg(reinterpret_cast<const float4*>(Asrc + (size_t)row * D + kcol) + k4);
            As[k4 * 4 + 0][m] = v.x;
            As[k4 * 4 + 1][m] = v.y;
            As[k4 * 4 + 2][m] = v.z;
            As[k4 * 4 + 3][m] = v.w;
        }

        // W tile: BK x BN
#pragma unroll
        for (int t = 0; t < (BK * BN / 4) / 256; t++) {
            int lin = tid + t * 256;
            int k = lin / (BN / 4);
            int n4 = lin % (BN / 4);
            int kk = kk0 + k;
            const float* Wp = (kk < 128) ? (Wl + (size_t)kk * BN)
                                         : (Wr + (size_t)(kk - 128) * BN);
            *reinterpret_cast<float4*>(&Ws[k][n4 * 4]) = __ldg(reinterpret_cast<const float4*>(Wp) + n4);
        }
        __syncthreads();

#pragma unroll
        for (int k = 0; k < BK; k++) {
            float4 r0 = *reinterpret_cast<const float4*>(&As[k][ty * 4]);
            float4 r1 = *reinterpret_cast<const float4*>(&As[k][64 + ty * 4]);
            float av[8] = {r0.x, r0.y, r0.z, r0.w, r1.x, r1.y, r1.z, r1.w};
            unsigned long long ap[8];
#pragma unroll
            for (int i = 0; i < 8; i++)
                asm("mov.b64 %0, {%1, %1};" : "=l"(ap[i]) : "f"(av[i]));

            unsigned long long bv[2 * NC];
#pragma unroll
            for (int c = 0; c < NC; c++) {
                bv[2 * c]     = *reinterpret_cast<const unsigned long long*>(&Ws[k][c * 64 + tx * 4]);
                bv[2 * c + 1] = *reinterpret_cast<const unsigned long long*>(&Ws[k][c * 64 + tx * 4 + 2]);
            }
#pragma unroll
            for (int i = 0; i < 8; i++)
#pragma unroll
                for (int j = 0; j < 2 * NC; j++)
                    asm("fma.rn.f32x2 %0, %1, %2, %0;" : "+l"(acc[i][j]) : "l"(ap[i]), "l"(bv[j]));
        }
        __syncthreads();
    }

    // epilogue: add bias, vectorized store
#pragma unroll
    for (int i = 0; i < 8; i++) {
        int row = rowBase + ((i < 4) ? (ty * 4 + i) : (64 + ty * 4 + i - 4));
        if (row >= N_NODES) continue;
#pragma unroll
        for (int c = 0; c < NC; c++) {
            float2 p0, p1;
            asm("mov.b64 {%0, %1}, %2;" : "=f"(p0.x), "=f"(p0.y) : "l"(acc[i][2 * c]));
            asm("mov.b64 {%0, %1}, %2;" : "=f"(p1.x), "=f"(p1.y) : "l"(acc[i][2 * c + 1]));
            float4 bb = __ldg(reinterpret_cast<const float4*>(bias) + (c * 16 + tx));
            float4 r = make_float4(p0.x + bb.x, p0.y + bb.y, p1.x + bb.z, p1.y + bb.w);
            *reinterpret_cast<float4*>(out + (size_t)row * BN + c * 64 + tx * 4) = r;
        }
    }
}

// ---------------- batch norm ------------------------------------------------
__global__ void k_bn_stats(const float* __restrict__ h, int n) {
    int col = threadIdx.x;      // blockDim = 128
    float s = 0.f, q = 0.f;
    for (int r = blockIdx.x; r < n; r += gridDim.x) {
        float v = h[(size_t)r * D + col];
        s += v;
        q += v * v;
    }
    atomicAdd(&g_colsum[col], s);
    atomicAdd(&g_colsq[col], q);
}

__global__ void k_bn_finalize(const float* __restrict__ gamma,
                              const float* __restrict__ beta) {
    int c = threadIdx.x;        // 128 threads, 1 block
    float mu = g_colsum[c] / (float)N_NODES;
    float var = g_colsq[c] / (float)N_NODES - mu * mu;
    float sc = gamma[c] * rsqrtf(var + BN_EPS);
    g_scale[c] = sc;
    g_shift[c] = beta[c] - mu * sc;
}

__global__ void k_bn_apply_relu(float* __restrict__ h, int total) {
    int i = blockIdx.x * blockDim.x + threadIdx.x;
    for (; i < total; i += gridDim.x * blockDim.x) {
        int c = i & (D - 1);
        float v = h[i] * g_scale[c] + g_shift[c];
        h[i] = fmaxf(v, 0.f);
    }
}

// ---------------- log-softmax over 64 cols (warp per row) ------------------
__global__ void k_logsoftmax(float* __restrict__ out, int n) {
    int row = blockIdx.x * 8 + (threadIdx.x >> 5);
    if (row >= n) return;
    int lane = threadIdx.x & 31;
    float* p = out + (size_t)row * D_OUT;
    float a = p[lane];
    float b = p[lane + 32];
    float m = fmaxf(a, b);
#pragma unroll
    for (int o = 16; o > 0; o >>= 1) m = fmaxf(m, __shfl_xor_sync(0xffffffffu, m, o));
    float e = expf(a - m) + expf(b - m);
#pragma unroll
    for (int o = 16; o > 0; o >>= 1) e += __shfl_xor_sync(0xffffffffu, e, o);
    float l = m + logf(e);
    p[lane] = a - l;
    p[lane + 32] = b - l;
}

// ---------------- launch ----------------------------------------------------
extern "C" void kernel_launch(void* const* d_in, const int* in_sizes, int n_in,
                              void* d_out, int out_size) {
    const float* x   = (const float*)d_in[0];
    const int* ei    = (const int*)d_in[1];
    const float* Wl0 = (const float*)d_in[2];
    const float* Wr0 = (const float*)d_in[3];
    const float* b0  = (const float*)d_in[4];
    const float* g0  = (const float*)d_in[5];
    const float* be0 = (const float*)d_in[6];
    const float* Wl1 = (const float*)d_in[7];
    const float* Wr1 = (const float*)d_in[8];
    const float* b1  = (const float*)d_in[9];
    const float* g1  = (const float*)d_in[10];
    const float* be1 = (const float*)d_in[11];
    const float* Wl2 = (const float*)d_in[12];
    const float* Wr2 = (const float*)d_in[13];
    const float* b2  = (const float*)d_in[14];
    float* out = (float*)d_out;

    const int E = in_sizes[1] / 2;
    const int* src = ei;
    const int* dst = ei + E;

    float *agg, *h0, *h1, *colsum, *colsq;
    int *cnti, *rowptr, *cursor, *csr;
    cudaGetSymbolAddress((void**)&agg, g_agg);
    cudaGetSymbolAddress((void**)&h0, g_h0);
    cudaGetSymbolAddress((void**)&h1, g_h1);
    cudaGetSymbolAddress((void**)&colsum, g_colsum);
    cudaGetSymbolAddress((void**)&colsq, g_colsq);
    cudaGetSymbolAddress((void**)&cnti, g_cnti);
    cudaGetSymbolAddress((void**)&rowptr, g_rowptr);
    cudaGetSymbolAddress((void**)&cursor, g_cursor);
    cudaGetSymbolAddress((void**)&csr, g_csr);

    const int aggBlocks  = (N_NODES * 32 + 255) / 256;
    const int gemmBlocks = (N_NODES + 127) / 128;

    // ---- CSR build (once per launch) ----
    k_zero_i<<<128, 256>>>(cnti, N_NODES);
    k_hist<<<1024, 256>>>(dst, E, cnti);
    k_scan<<<1, 1024>>>(cnti, rowptr, cursor);
    k_fill<<<1024, 256>>>(src, dst, E, cursor, csr);

    // ---- layer 0 ----
    k_aggregate<<<aggBlocks, 256>>>(x, csr, rowptr, agg);
    k_sage_gemm<128><<<gemmBlocks, 256>>>(agg, x, Wl0, Wr0, b0, h0);
    k_zero_f<<<1, 128>>>(colsum, D);
    k_zero_f<<<1, 128>>>(colsq, D);
    k_bn_stats<<<512, 128>>>(h0, N_NODES);
    k_bn_finalize<<<1, 128>>>(g0, be0);
    k_bn_apply_relu<<<2048, 256>>>(h0, N_NODES * D);

    // ---- layer 1 ----
    k_aggregate<<<aggBlocks, 256>>>(h0, csr, rowptr, agg);
    k_sage_gemm<128><<<gemmBlocks, 256>>>(agg, h0, Wl1, Wr1, b1, h1);
    k_zero_f<<<1, 128>>>(colsum, D);
    k_zero_f<<<1, 128>>>(colsq, D);
    k_bn_stats<<<512, 128>>>(h1, N_NODES);
    k_bn_finalize<<<1, 128>>>(g1, be1);
    k_bn_apply_relu<<<2048, 256>>>(h1, N_NODES * D);

    // ---- layer 2 ----
    k_aggregate<<<aggBlocks, 256>>>(h1, csr, rowptr, agg);
    k_sage_gemm<64><<<gemmBlocks, 256>>>(agg, h1, Wl2, Wr2, b2, out);
    k_logsoftmax<<<(N_NODES + 7) / 8, 256>>>(out, N_NODES);
}

// round 5
// speedup vs baseline: 1.7058x; 1.1809x over previous
#include <cuda_runtime.h>
#include <cuda_bf16.h>
#include <cstdint>

#define N_NODES 50000
#define E_MAX   800000
#define D 128
#define KTOT 256
#define D_OUT 64
#define BN_EPS 1e-5f

// ---------------- scratch (device globals; no allocation allowed) ----------
__device__ __nv_bfloat16 g_Ahi[(size_t)N_NODES * KTOT];  // [mean | self] hi
__device__ __nv_bfloat16 g_Alo[(size_t)N_NODES * KTOT];  // [mean | self] lo
__device__ __nv_bfloat16 g_Whi[(size_t)(128 + 128 + 64) * KTOT];
__device__ __nv_bfloat16 g_Wlo[(size_t)(128 + 128 + 64) * KTOT];
__device__ float g_h0[(size_t)N_NODES * D];
__device__ float g_h1[(size_t)N_NODES * D];
__device__ int   g_cnti[N_NODES];
__device__ int   g_rowptr[N_NODES + 1];
__device__ int   g_cursor[N_NODES];
__device__ int   g_csr[E_MAX];
__device__ float g_colsum[D];
__device__ float g_colsq[D];
__device__ float g_scale[D];
__device__ float g_shift[D];

// ---------------- helpers ----------------------------------------------------
__device__ __forceinline__ uint32_t smem_u32(const void* p) {
    return (uint32_t)__cvta_generic_to_shared(p);
}

__device__ __forceinline__ void ldsm4(uint32_t* r, uint32_t a) {
    asm volatile("ldmatrix.sync.aligned.m8n8.x4.shared.b16 {%0,%1,%2,%3}, [%4];"
                 : "=r"(r[0]), "=r"(r[1]), "=r"(r[2]), "=r"(r[3]) : "r"(a));
}

__device__ __forceinline__ void mma16816(float* d, const uint32_t* a, const uint32_t* b) {
    asm volatile("mma.sync.aligned.m16n8k16.row.col.f32.bf16.bf16.f32 "
                 "{%0,%1,%2,%3}, {%4,%5,%6,%7}, {%8,%9}, {%0,%1,%2,%3};"
                 : "+f"(d[0]), "+f"(d[1]), "+f"(d[2]), "+f"(d[3])
                 : "r"(a[0]), "r"(a[1]), "r"(a[2]), "r"(a[3]), "r"(b[0]), "r"(b[1]));
}

__device__ __forceinline__ void bf16split(float v, __nv_bfloat16& hi, __nv_bfloat16& lo) {
    hi = __float2bfloat16(v);
    lo = __float2bfloat16(v - __bfloat162float(hi));
}

// ---------------- small utils ----------------------------------------------
__global__ void k_zero_i(int* __restrict__ p, int n) {
    int i = blockIdx.x * blockDim.x + threadIdx.x;
    for (; i < n; i += gridDim.x * blockDim.x) p[i] = 0;
}

// ---------------- CSR build -------------------------------------------------
__global__ void k_hist(const int* __restrict__ dst, int E, int* __restrict__ cnt) {
    int e = blockIdx.x * blockDim.x + threadIdx.x;
    for (; e < E; e += gridDim.x * blockDim.x)
        atomicAdd(&cnt[dst[e]], 1);
}

__global__ void k_scan(const int* __restrict__ cnt, int* __restrict__ row_ptr,
                       int* __restrict__ cursor) {
    constexpr int SEG = (N_NODES + 1023) / 1024;
    int t = threadIdx.x;
    int beg = t * SEG;
    int end = min(beg + SEG, N_NODES);
    int s = 0;
    for (int i = beg; i < end; i++) s += cnt[i];
    __shared__ int sh[1024];
    sh[t] = s;
    __syncthreads();
    for (int off = 1; off < 1024; off <<= 1) {
        int v = (t >= off) ? sh[t - off] : 0;
        __syncthreads();
        sh[t] += v;
        __syncthreads();
    }
    int pos = sh[t] - s;
    for (int i = beg; i < end; i++) {
        row_ptr[i] = pos;
        cursor[i]  = pos;
        pos += cnt[i];
    }
    if (beg < N_NODES && end == N_NODES) row_ptr[N_NODES] = pos;
}

__global__ void k_fill(const int* __restrict__ src, const int* __restrict__ dst,
                       int E, int* __restrict__ cursor, int* __restrict__ csr) {
    int e = blockIdx.x * blockDim.x + threadIdx.x;
    for (; e < E; e += gridDim.x * blockDim.x) {
        int d = dst[e];
        int p = atomicAdd(&cursor[d], 1);
        csr[p] = src[e];
    }
}

// ---------------- gather aggregation -> bf16 hi/lo (A cols 0..127) ---------
__global__ __launch_bounds__(256)
void k_aggregate(const float* __restrict__ xin, const int* __restrict__ csr,
                 const int* __restrict__ row_ptr,
                 __nv_bfloat16* __restrict__ Ahi, __nv_bfloat16* __restrict__ Alo) {
    int w = (blockIdx.x * blockDim.x + threadIdx.x) >> 5;
    if (w >= N_NODES) return;
    int lane = threadIdx.x & 31;
    int beg = __ldg(row_ptr + w);
    int end = __ldg(row_ptr + w + 1);
    float4 a0 = make_float4(0.f, 0.f, 0.f, 0.f);
    float4 a1 = make_float4(0.f, 0.f, 0.f, 0.f);
    int i = beg;
    for (; i + 1 < end; i += 2) {
        int s0 = __ldg(csr + i);
        int s1 = __ldg(csr + i + 1);
        float4 v0 = __ldg(reinterpret_cast<const float4*>(xin + (size_t)s0 * D) + lane);
        float4 v1 = __ldg(reinterpret_cast<const float4*>(xin + (size_t)s1 * D) + lane);
        a0.x += v0.x; a0.y += v0.y; a0.z += v0.z; a0.w += v0.w;
        a1.x += v1.x; a1.y += v1.y; a1.z += v1.z; a1.w += v1.w;
    }
    if (i < end) {
        int s0 = __ldg(csr + i);
        float4 v0 = __ldg(reinterpret_cast<const float4*>(xin + (size_t)s0 * D) + lane);
        a0.x += v0.x; a0.y += v0.y; a0.z += v0.z; a0.w += v0.w;
    }
    float inv = 1.f / (float)max(end - beg, 1);
    float v[4] = {(a0.x + a1.x) * inv, (a0.y + a1.y) * inv,
                  (a0.z + a1.z) * inv, (a0.w + a1.w) * inv};
    __nv_bfloat16 hb[4], lb[4];
#pragma unroll
    for (int j = 0; j < 4; j++) bf16split(v[j], hb[j], lb[j]);
    size_t off = (size_t)w * KTOT + lane * 4;
    *reinterpret_cast<uint2*>(Ahi + off) = *reinterpret_cast<uint2*>(hb);
    *reinterpret_cast<uint2*>(Alo + off) = *reinterpret_cast<uint2*>(lb);
}

// ---------------- x -> bf16 hi/lo self term (A cols 128..255) ---------------
__global__ void k_convert_x(const float* __restrict__ xin,
                            __nv_bfloat16* __restrict__ Ahi,
                            __nv_bfloat16* __restrict__ Alo) {
    int i4 = blockIdx.x * blockDim.x + threadIdx.x;
    const int total4 = N_NODES * D / 4;
    for (; i4 < total4; i4 += gridDim.x * blockDim.x) {
        int row = i4 >> 5;
        int c4 = (i4 & 31) * 4;
        float4 v = __ldg(reinterpret_cast<const float4*>(xin) + i4);
        float a[4] = {v.x, v.y, v.z, v.w};
        __nv_bfloat16 hb[4], lb[4];
#pragma unroll
        for (int j = 0; j < 4; j++) bf16split(a[j], hb[j], lb[j]);
        size_t off = (size_t)row * KTOT + 128 + c4;
        *reinterpret_cast<uint2*>(Ahi + off) = *reinterpret_cast<uint2*>(hb);
        *reinterpret_cast<uint2*>(Alo + off) = *reinterpret_cast<uint2*>(lb);
    }
}

// ---------------- weight convert: [Wl;Wr] -> transposed bf16 hi/lo ---------
__global__ void k_convert_w(const float* __restrict__ Wl, const float* __restrict__ Wr,
                            __nv_bfloat16* __restrict__ Whi, __nv_bfloat16* __restrict__ Wlo,
                            int BN) {
    int idx = blockIdx.x * blockDim.x + threadIdx.x;
    int total = BN * KTOT;
    if (idx >= total) return;
    int n = idx >> 8;
    int k = idx & 255;
    float v = (k < 128) ? __ldg(Wl + (size_t)k * BN + n)
                        : __ldg(Wr + (size_t)(k - 128) * BN + n);
    __nv_bfloat16 h, l;
    bf16split(v, h, l);
    Whi[idx] = h;
    Wlo[idx] = l;
}

// ---------------- HMMA fused SAGE GEMM --------------------------------------
// out[128 x BN] = A[128 x 256] @ W^T (+bias), A/W bf16 hi/lo split:
// acc = Ah*Wh + Al*Wh + Ah*Wl, fp32 accumulators via mma.sync m16n8k16.
template <int BN>
__global__ __launch_bounds__(256)
void k_mma_gemm(const __nv_bfloat16* __restrict__ Ahi, const __nv_bfloat16* __restrict__ Alo,
                const __nv_bfloat16* __restrict__ Whi, const __nv_bfloat16* __restrict__ Wlo,
                const float* __restrict__ bias, float* __restrict__ out) {
    constexpr int RS = 72;           // bf16 per smem row (64 data + 8 pad = 144B)
    constexpr int NT = BN / 16;      // n-tiles per warp (8 or 4)
    extern __shared__ __nv_bfloat16 sm[];
    __nv_bfloat16* sAh = sm;
    __nv_bfloat16* sAl = sm + 128 * RS;
    __nv_bfloat16* sWh = sm + 2 * 128 * RS;
    __nv_bfloat16* sWl = sWh + BN * RS;

    const int tid = threadIdx.x;
    const int lane = tid & 31;
    const int warp = tid >> 5;
    const int wr = warp & 3;
    const int wc = warp >> 2;
    const int rowBase = blockIdx.x * 128;

    const uint32_t sbAh = smem_u32(sAh);
    const uint32_t sbAl = smem_u32(sAl);
    const uint32_t sbWh = smem_u32(sWh);
    const uint32_t sbWl = smem_u32(sWl);

    float acc[2][NT][4];
#pragma unroll
    for (int mt = 0; mt < 2; mt++)
#pragma unroll
        for (int nt = 0; nt < NT; nt++)
#pragma unroll
            for (int j = 0; j < 4; j++) acc[mt][nt][j] = 0.f;

    for (int stage = 0; stage < 4; stage++) {
        // A tiles: 128 rows x 64 bf16 (hi & lo)
#pragma unroll
        for (int t = 0; t < 4; t++) {
            int idx = tid + t * 256;
            int r = idx >> 3, c = idx & 7;
            int row = rowBase + r;
            uint4 vh = make_uint4(0, 0, 0, 0), vl = make_uint4(0, 0, 0, 0);
            if (row < N_NODES) {
                vh = __ldg(reinterpret_cast<const uint4*>(Ahi + (size_t)row * KTOT + stage * 64) + c);
                vl = __ldg(reinterpret_cast<const uint4*>(Alo + (size_t)row * KTOT + stage * 64) + c);
            }
            *reinterpret_cast<uint4*>(sAh + r * RS + c * 8) = vh;
            *reinterpret_cast<uint4*>(sAl + r * RS + c * 8) = vl;
        }
        // W tiles: BN rows x 64 bf16 (hi & lo)
#pragma unroll
        for (int t = 0; t < BN * 8 / 256; t++) {
            int idx = tid + t * 256;
            int n = idx >> 3, c = idx & 7;
            uint4 vh = __ldg(reinterpret_cast<const uint4*>(Whi + (size_t)n * KTOT + stage * 64) + c);
            uint4 vl = __ldg(reinterpret_cast<const uint4*>(Wlo + (size_t)n * KTOT + stage * 64) + c);
            *reinterpret_cast<uint4*>(sWh + n * RS + c * 8) = vh;
            *reinterpret_cast<uint4*>(sWl + n * RS + c * 8) = vl;
        }
        __syncthreads();

#pragma unroll
        for (int ks = 0; ks < 4; ks++) {
            const int k0 = ks * 16;
            const uint32_t koff = (uint32_t)(k0 + (lane >> 4) * 8) * 2;

            uint32_t ah[2][4], al[2][4];
#pragma unroll
            for (int mt = 0; mt < 2; mt++) {
                uint32_t roff = (uint32_t)(wr * 32 + mt * 16 + (lane & 15)) * (RS * 2) + koff;
                ldsm4(ah[mt], sbAh + roff);
                ldsm4(al[mt], sbAl + roff);
            }
            uint32_t bh[NT][2], bl[NT][2];
#pragma unroll
            for (int g = 0; g < NT / 2; g++) {
                uint32_t roff = (uint32_t)(wc * (BN / 2) + g * 16 + (lane & 15)) * (RS * 2) + koff;
                uint32_t r[4];
                ldsm4(r, sbWh + roff);
                bh[2 * g][0] = r[0]; bh[2 * g][1] = r[2];
                bh[2 * g + 1][0] = r[1]; bh[2 * g + 1][1] = r[3];
                ldsm4(r, sbWl + roff);
                bl[2 * g][0] = r[0]; bl[2 * g][1] = r[2];
                bl[2 * g + 1][0] = r[1]; bl[2 * g + 1][1] = r[3];
            }
#pragma unroll
            for (int mt = 0; mt < 2; mt++)
#pragma unroll
                for (int nt = 0; nt < NT; nt++) {
                    mma16816(acc[mt][nt], ah[mt], bh[nt]);
                    mma16816(acc[mt][nt], al[mt], bh[nt]);
                    mma16816(acc[mt][nt], ah[mt], bl[nt]);
                }
        }
        __syncthreads();
    }

    // epilogue: bias + store (float2 per fragment row)
#pragma unroll
    for (int mt = 0; mt < 2; mt++) {
        int r0 = rowBase + wr * 32 + mt * 16 + (lane >> 2);
#pragma unroll
        for (int nt = 0; nt < NT; nt++) {
            int col = wc * (BN / 2) + nt * 8 + (lane & 3) * 2;
            float2 bb = *reinterpret_cast<const float2*>(bias + col);
            if (r0 < N_NODES) {
                float2 v = make_float2(acc[mt][nt][0] + bb.x, acc[mt][nt][1] + bb.y);
                *reinterpret_cast<float2*>(out + (size_t)r0 * BN + col) = v;
            }
            if (r0 + 8 < N_NODES) {
                float2 v = make_float2(acc[mt][nt][2] + bb.x, acc[mt][nt][3] + bb.y);
                *reinterpret_cast<float2*>(out + (size_t)(r0 + 8) * BN + col) = v;
            }
        }
    }
}

// ---------------- batch norm ------------------------------------------------
__global__ void k_bn_stats(const float* __restrict__ h, int n) {
    int col = threadIdx.x;
    float s = 0.f, q = 0.f;
    for (int r = blockIdx.x; r < n; r += gridDim.x) {
        float v = h[(size_t)r * D + col];
        s += v;
        q += v * v;
    }
    atomicAdd(&g_colsum[col], s);
    atomicAdd(&g_colsq[col], q);
}

__global__ void k_bn_finalize(const float* __restrict__ gamma,
                              const float* __restrict__ beta) {
    int c = threadIdx.x;
    float mu = g_colsum[c] / (float)N_NODES;
    float var = g_colsq[c] / (float)N_NODES - mu * mu;
    float sc = gamma[c] * rsqrtf(var + BN_EPS);
    g_scale[c] = sc;
    g_shift[c] = beta[c] - mu * sc;
    g_colsum[c] = 0.f;   // self-restore for next layer / next replay
    g_colsq[c] = 0.f;
}

// apply BN+ReLU in place on h, and emit bf16 hi/lo self term into A cols 128..255
__global__ void k_bn_apply_relu(float* __restrict__ h,
                                __nv_bfloat16* __restrict__ Ahi,
                                __nv_bfloat16* __restrict__ Alo) {
    int i4 = blockIdx.x * blockDim.x + threadIdx.x;
    const int total4 = N_NODES * D / 4;
    for (; i4 < total4; i4 += gridDim.x * blockDim.x) {
        int row = i4 >> 5;
        int c4 = (i4 & 31) * 4;
        float4 v = *(reinterpret_cast<float4*>(h) + i4);
        float a[4];
        a[0] = fmaxf(v.x * g_scale[c4 + 0] + g_shift[c4 + 0], 0.f);
        a[1] = fmaxf(v.y * g_scale[c4 + 1] + g_shift[c4 + 1], 0.f);
        a[2] = fmaxf(v.z * g_scale[c4 + 2] + g_shift[c4 + 2], 0.f);
        a[3] = fmaxf(v.w * g_scale[c4 + 3] + g_shift[c4 + 3], 0.f);
        *(reinterpret_cast<float4*>(h) + i4) = make_float4(a[0], a[1], a[2], a[3]);
        __nv_bfloat16 hb[4], lb[4];
#pragma unroll
        for (int j = 0; j < 4; j++) bf16split(a[j], hb[j], lb[j]);
        size_t off = (size_t)row * KTOT + 128 + c4;
        *reinterpret_cast<uint2*>(Ahi + off) = *reinterpret_cast<uint2*>(hb);
        *reinterpret_cast<uint2*>(Alo + off) = *reinterpret_cast<uint2*>(lb);
    }
}

// ---------------- log-softmax over 64 cols (warp per row) ------------------
__global__ void k_logsoftmax(float* __restrict__ out, int n) {
    int row = blockIdx.x * 8 + (threadIdx.x >> 5);
    if (row >= n) return;
    int lane = threadIdx.x & 31;
    float* p = out + (size_t)row * D_OUT;
    float a = p[lane];
    float b = p[lane + 32];
    float m = fmaxf(a, b);
#pragma unroll
    for (int o = 16; o > 0; o >>= 1) m = fmaxf(m, __shfl_xor_sync(0xffffffffu, m, o));
    float e = expf(a - m) + expf(b - m);
#pragma unroll
    for (int o = 16; o > 0; o >>= 1) e += __shfl_xor_sync(0xffffffffu, e, o);
    float l = m + logf(e);
    p[lane] = a - l;
    p[lane + 32] = b - l;
}

// ---------------- launch ----------------------------------------------------
extern "C" void kernel_launch(void* const* d_in, const int* in_sizes, int n_in,
                              void* d_out, int out_size) {
    const float* x   = (const float*)d_in[0];
    const int* ei    = (const int*)d_in[1];
    const float* Wl0 = (const float*)d_in[2];
    const float* Wr0 = (const float*)d_in[3];
    const float* b0  = (const float*)d_in[4];
    const float* g0  = (const float*)d_in[5];
    const float* be0 = (const float*)d_in[6];
    const float* Wl1 = (const float*)d_in[7];
    const float* Wr1 = (const float*)d_in[8];
    const float* b1  = (const float*)d_in[9];
    const float* g1  = (const float*)d_in[10];
    const float* be1 = (const float*)d_in[11];
    const float* Wl2 = (const float*)d_in[12];
    const float* Wr2 = (const float*)d_in[13];
    const float* b2  = (const float*)d_in[14];
    float* out = (float*)d_out;

    const int E = in_sizes[1] / 2;
    const int* src = ei;
    const int* dst = ei + E;

    float *h0, *h1;
    __nv_bfloat16 *Ahi, *Alo, *Whi, *Wlo;
    int *cnti, *rowptr, *cursor, *csr;
    cudaGetSymbolAddress((void**)&h0, g_h0);
    cudaGetSymbolAddress((void**)&h1, g_h1);
    cudaGetSymbolAddress((void**)&Ahi, g_Ahi);
    cudaGetSymbolAddress((void**)&Alo, g_Alo);
    cudaGetSymbolAddress((void**)&Whi, g_Whi);
    cudaGetSymbolAddress((void**)&Wlo, g_Wlo);
    cudaGetSymbolAddress((void**)&cnti, g_cnti);
    cudaGetSymbolAddress((void**)&rowptr, g_rowptr);
    cudaGetSymbolAddress((void**)&cursor, g_cursor);
    cudaGetSymbolAddress((void**)&csr, g_csr);

    constexpr int RS = 72;
    const int SMEM128 = (2 * 128 + 2 * 128) * RS * 2;  // 73728
    const int SMEM64  = (2 * 128 + 2 * 64) * RS * 2;   // 55296
    cudaFuncSetAttribute(k_mma_gemm<128>, cudaFuncAttributeMaxDynamicSharedMemorySize, SMEM128);
    cudaFuncSetAttribute(k_mma_gemm<64>,  cudaFuncAttributeMaxDynamicSharedMemorySize, SMEM64);

    const int aggBlocks  = (N_NODES * 32 + 255) / 256;
    const int gemmBlocks = (N_NODES + 127) / 128;

    __nv_bfloat16* W0h = Whi;               __nv_bfloat16* W0l = Wlo;
    __nv_bfloat16* W1h = Whi + 128 * KTOT;  __nv_bfloat16* W1l = Wlo + 128 * KTOT;
    __nv_bfloat16* W2h = Whi + 256 * KTOT;  __nv_bfloat16* W2l = Wlo + 256 * KTOT;

    // ---- CSR build + weight conversion ----
    k_zero_i<<<128, 256>>>(cnti, N_NODES);
    k_hist<<<1024, 256>>>(dst, E, cnti);
    k_scan<<<1, 1024>>>(cnti, rowptr, cursor);
    k_fill<<<1024, 256>>>(src, dst, E, cursor, csr);
    k_convert_w<<<128, 256>>>(Wl0, Wr0, W0h, W0l, 128);
    k_convert_w<<<128, 256>>>(Wl1, Wr1, W1h, W1l, 128);
    k_convert_w<<<64, 256>>>(Wl2, Wr2, W2h, W2l, 64);

    // ---- layer 0 ----
    k_convert_x<<<2048, 256>>>(x, Ahi, Alo);
    k_aggregate<<<aggBlocks, 256>>>(x, csr, rowptr, Ahi, Alo);
    k_mma_gemm<128><<<gemmBlocks, 256, SMEM128>>>(Ahi, Alo, W0h, W0l, b0, h0);
    k_bn_stats<<<512, 128>>>(h0, N_NODES);
    k_bn_finalize<<<1, 128>>>(g0, be0);
    k_bn_apply_relu<<<2048, 256>>>(h0, Ahi, Alo);

    // ---- layer 1 ----
    k_aggregate<<<aggBlocks, 256>>>(h0, csr, rowptr, Ahi, Alo);
    k_mma_gemm<128><<<gemmBlocks, 256, SMEM128>>>(Ahi, Alo, W1h, W1l, b1, h1);
    k_bn_stats<<<512, 128>>>(h1, N_NODES);
    k_bn_finalize<<<1, 128>>>(g1, be1);
    k_bn_apply_relu<<<2048, 256>>>(h1, Ahi, Alo);

    // ---- layer 2 ----
    k_aggregate<<<aggBlocks, 256>>>(h1, csr, rowptr, Ahi, Alo);
    k_mma_gemm<64><<<gemmBlocks, 256, SMEM64>>>(Ahi, Alo, W2h, W2l, b2, out);
    k_logsoftmax<<<(N_NODES + 7) / 8, 256>>>(out, N_NODES);
}

// round 6
// speedup vs baseline: 1.9098x; 1.1196x over previous
#include <cuda_runtime.h>
#include <cuda_bf16.h>
#include <cstdint>

#define N_NODES 50000
#define E_MAX   800000
#define D 128
#define KTOT 256
#define D_OUT 64
#define BN_EPS 1e-5f

// ---------------- scratch (device globals; no allocation allowed) ----------
__device__ __nv_bfloat16 g_Ahi[(size_t)N_NODES * KTOT];  // [mean | self] hi
__device__ __nv_bfloat16 g_Alo[(size_t)N_NODES * KTOT];  // [mean | self] lo
__device__ __nv_bfloat16 g_Whi[(size_t)(128 + 128 + 64) * KTOT];
__device__ __nv_bfloat16 g_Wlo[(size_t)(128 + 128 + 64) * KTOT];
__device__ float g_h0[(size_t)N_NODES * D];
__device__ float g_h1[(size_t)N_NODES * D];
__device__ int   g_cnti[N_NODES];
__device__ int   g_rowptr[N_NODES + 1];
__device__ int   g_cursor[N_NODES];
__device__ int   g_csr[E_MAX];
__device__ float g_colsum[D];
__device__ float g_colsq[D];
__device__ float g_scale[D];
__device__ float g_shift[D];

// ---------------- helpers ----------------------------------------------------
__device__ __forceinline__ uint32_t smem_u32(const void* p) {
    return (uint32_t)__cvta_generic_to_shared(p);
}

__device__ __forceinline__ void ldsm4(uint32_t* r, uint32_t a) {
    asm volatile("ldmatrix.sync.aligned.m8n8.x4.shared.b16 {%0,%1,%2,%3}, [%4];"
                 : "=r"(r[0]), "=r"(r[1]), "=r"(r[2]), "=r"(r[3]) : "r"(a));
}

__device__ __forceinline__ void mma16816(float* d, const uint32_t* a, const uint32_t* b) {
    asm volatile("mma.sync.aligned.m16n8k16.row.col.f32.bf16.bf16.f32 "
                 "{%0,%1,%2,%3}, {%4,%5,%6,%7}, {%8,%9}, {%0,%1,%2,%3};"
                 : "+f"(d[0]), "+f"(d[1]), "+f"(d[2]), "+f"(d[3])
                 : "r"(a[0]), "r"(a[1]), "r"(a[2]), "r"(a[3]), "r"(b[0]), "r"(b[1]));
}

__device__ __forceinline__ void bf16split(float v, __nv_bfloat16& hi, __nv_bfloat16& lo) {
    hi = __float2bfloat16(v);
    lo = __float2bfloat16(v - __bfloat162float(hi));
}

// ---------------- small utils ----------------------------------------------
__global__ void k_zero_i(int* __restrict__ p, int n) {
    int i = blockIdx.x * blockDim.x + threadIdx.x;
    for (; i < n; i += gridDim.x * blockDim.x) p[i] = 0;
}

// ---------------- CSR build -------------------------------------------------
__global__ void k_hist(const int* __restrict__ dst, int E, int* __restrict__ cnt) {
    int e = blockIdx.x * blockDim.x + threadIdx.x;
    for (; e < E; e += gridDim.x * blockDim.x)
        atomicAdd(&cnt[dst[e]], 1);
}

__global__ void k_scan(const int* __restrict__ cnt, int* __restrict__ row_ptr,
                       int* __restrict__ cursor) {
    constexpr int SEG = (N_NODES + 1023) / 1024;
    int t = threadIdx.x;
    int beg = t * SEG;
    int end = min(beg + SEG, N_NODES);
    int s = 0;
    for (int i = beg; i < end; i++) s += cnt[i];
    __shared__ int sh[1024];
    sh[t] = s;
    __syncthreads();
    for (int off = 1; off < 1024; off <<= 1) {
        int v = (t >= off) ? sh[t - off] : 0;
        __syncthreads();
        sh[t] += v;
        __syncthreads();
    }
    int pos = sh[t] - s;
    for (int i = beg; i < end; i++) {
        row_ptr[i] = pos;
        cursor[i]  = pos;
        pos += cnt[i];
    }
    if (beg < N_NODES && end == N_NODES) row_ptr[N_NODES] = pos;
}

__global__ void k_fill(const int* __restrict__ src, const int* __restrict__ dst,
                       int E, int* __restrict__ cursor, int* __restrict__ csr) {
    int e = blockIdx.x * blockDim.x + threadIdx.x;
    for (; e < E; e += gridDim.x * blockDim.x) {
        int d = dst[e];
        int p = atomicAdd(&cursor[d], 1);
        csr[p] = src[e];
    }
}

// ---------------- gather aggregation -> bf16 hi/lo (A cols 0..127) ---------
// L0 = true: source is fp32 x; also emits the self term (cols 128..255).
// L0 = false: source is the bf16 hi/lo self-columns written by bn_apply.
template <bool L0>
__global__ __launch_bounds__(256)
void k_aggregate(const float* __restrict__ xin, const int* __restrict__ csr,
                 const int* __restrict__ row_ptr,
                 __nv_bfloat16* __restrict__ Ahi, __nv_bfloat16* __restrict__ Alo) {
    int w = (blockIdx.x * blockDim.x + threadIdx.x) >> 5;
    if (w >= N_NODES) return;
    int lane = threadIdx.x & 31;
    int beg = __ldg(row_ptr + w);
    int end = __ldg(row_ptr + w + 1);
    float4 a0 = make_float4(0.f, 0.f, 0.f, 0.f);
    float4 a1 = make_float4(0.f, 0.f, 0.f, 0.f);

    if (L0) {
        int i = beg;
        for (; i + 1 < end; i += 2) {
            int s0 = __ldg(csr + i);
            int s1 = __ldg(csr + i + 1);
            float4 v0 = __ldg(reinterpret_cast<const float4*>(xin + (size_t)s0 * D) + lane);
            float4 v1 = __ldg(reinterpret_cast<const float4*>(xin + (size_t)s1 * D) + lane);
            a0.x += v0.x; a0.y += v0.y; a0.z += v0.z; a0.w += v0.w;
            a1.x += v1.x; a1.y += v1.y; a1.z += v1.z; a1.w += v1.w;
        }
        if (i < end) {
            int s0 = __ldg(csr + i);
            float4 v0 = __ldg(reinterpret_cast<const float4*>(xin + (size_t)s0 * D) + lane);
            a0.x += v0.x; a0.y += v0.y; a0.z += v0.z; a0.w += v0.w;
        }
    } else {
        for (int i = beg; i < end; i++) {
            int s0 = __ldg(csr + i);
            size_t base = (size_t)s0 * KTOT + 128 + lane * 4;
            uint2 uh = __ldg(reinterpret_cast<const uint2*>(Ahi + base));
            uint2 ul = __ldg(reinterpret_cast<const uint2*>(Alo + base));
            float2 h0 = __bfloat1622float2(*reinterpret_cast<__nv_bfloat162*>(&uh.x));
            float2 h1 = __bfloat1622float2(*reinterpret_cast<__nv_bfloat162*>(&uh.y));
            float2 l0 = __bfloat1622float2(*reinterpret_cast<__nv_bfloat162*>(&ul.x));
            float2 l1 = __bfloat1622float2(*reinterpret_cast<__nv_bfloat162*>(&ul.y));
            a0.x += h0.x + l0.x; a0.y += h0.y + l0.y;
            a0.z += h1.x + l1.x; a0.w += h1.y + l1.y;
        }
    }

    float inv = 1.f / (float)max(end - beg, 1);
    float v[4] = {(a0.x + a1.x) * inv, (a0.y + a1.y) * inv,
                  (a0.z + a1.z) * inv, (a0.w + a1.w) * inv};
    __nv_bfloat16 hb[4], lb[4];
#pragma unroll
    for (int j = 0; j < 4; j++) bf16split(v[j], hb[j], lb[j]);
    size_t off = (size_t)w * KTOT + lane * 4;
    *reinterpret_cast<uint2*>(Ahi + off) = *reinterpret_cast<uint2*>(hb);
    *reinterpret_cast<uint2*>(Alo + off) = *reinterpret_cast<uint2*>(lb);

    if (L0) {
        // fused self-term conversion (was k_convert_x)
        float4 xv = __ldg(reinterpret_cast<const float4*>(xin + (size_t)w * D) + lane);
        float s[4] = {xv.x, xv.y, xv.z, xv.w};
        __nv_bfloat16 shb[4], slb[4];
#pragma unroll
        for (int j = 0; j < 4; j++) bf16split(s[j], shb[j], slb[j]);
        *reinterpret_cast<uint2*>(Ahi + off + 128) = *reinterpret_cast<uint2*>(shb);
        *reinterpret_cast<uint2*>(Alo + off + 128) = *reinterpret_cast<uint2*>(slb);
    }
}

// ---------------- weight convert: all 3 layers in one launch ----------------
__global__ void k_convert_w(const float* __restrict__ Wl0, const float* __restrict__ Wr0,
                            const float* __restrict__ Wl1, const float* __restrict__ Wr1,
                            const float* __restrict__ Wl2, const float* __restrict__ Wr2,
                            __nv_bfloat16* __restrict__ Whi, __nv_bfloat16* __restrict__ Wlo) {
    int idx = blockIdx.x * blockDim.x + threadIdx.x;
    const int T01 = 128 * KTOT;
    const int total = 2 * T01 + 64 * KTOT;
    if (idx >= total) return;
    const float *Wl, *Wr;
    int local, BN;
    if (idx < T01) { Wl = Wl0; Wr = Wr0; local = idx; BN = 128; }
    else if (idx < 2 * T01) { Wl = Wl1; Wr = Wr1; local = idx - T01; BN = 128; }
    else { Wl = Wl2; Wr = Wr2; local = idx - 2 * T01; BN = 64; }
    int n = local >> 8;
    int k = local & 255;
    float v = (k < 128) ? __ldg(Wl + (size_t)k * BN + n)
                        : __ldg(Wr + (size_t)(k - 128) * BN + n);
    __nv_bfloat16 h, l;
    bf16split(v, h, l);
    Whi[idx] = h;
    Wlo[idx] = l;
}

// ---------------- HMMA fused SAGE GEMM --------------------------------------
// out[128 x BN] = A[128 x 256] @ W^T (+bias); acc = Ah*Wh + Al*Wh + Ah*Wl.
// MODE 0: store h + fused BN column stats.  MODE 1: fused log-softmax to out.
template <int BN, int MODE>
__global__ __launch_bounds__(256)
void k_mma_gemm(const __nv_bfloat16* __restrict__ Ahi, const __nv_bfloat16* __restrict__ Alo,
                const __nv_bfloat16* __restrict__ Whi, const __nv_bfloat16* __restrict__ Wlo,
                const float* __restrict__ bias, float* __restrict__ out) {
    constexpr int RS = 72;           // bf16 per smem row (64 data + 8 pad = 144B)
    constexpr int NT = BN / 16;      // n-tiles per warp (8 or 4)
    extern __shared__ __nv_bfloat16 sm[];
    __nv_bfloat16* sAh = sm;
    __nv_bfloat16* sAl = sm + 128 * RS;
    __nv_bfloat16* sWh = sm + 2 * 128 * RS;
    __nv_bfloat16* sWl = sWh + BN * RS;

    __shared__ float ssum[128];
    __shared__ float ssq[128];

    const int tid = threadIdx.x;
    const int lane = tid & 31;
    const int warp = tid >> 5;
    const int wr = warp & 3;
    const int wc = warp >> 2;
    const int rowBase = blockIdx.x * 128;

    if (MODE == 0 && tid < BN) { ssum[tid] = 0.f; ssq[tid] = 0.f; }

    const uint32_t sbAh = smem_u32(sAh);
    const uint32_t sbAl = smem_u32(sAl);
    const uint32_t sbWh = smem_u32(sWh);
    const uint32_t sbWl = smem_u32(sWl);

    float acc[2][NT][4];
#pragma unroll
    for (int mt = 0; mt < 2; mt++)
#pragma unroll
        for (int nt = 0; nt < NT; nt++)
#pragma unroll
            for (int j = 0; j < 4; j++) acc[mt][nt][j] = 0.f;

    for (int stage = 0; stage < 4; stage++) {
#pragma unroll
        for (int t = 0; t < 4; t++) {
            int idx = tid + t * 256;
            int r = idx >> 3, c = idx & 7;
            int row = rowBase + r;
            uint4 vh = make_uint4(0, 0, 0, 0), vl = make_uint4(0, 0, 0, 0);
            if (row < N_NODES) {
                vh = __ldg(reinterpret_cast<const uint4*>(Ahi + (size_t)row * KTOT + stage * 64) + c);
                vl = __ldg(reinterpret_cast<const uint4*>(Alo + (size_t)row * KTOT + stage * 64) + c);
            }
            *reinterpret_cast<uint4*>(sAh + r * RS + c * 8) = vh;
            *reinterpret_cast<uint4*>(sAl + r * RS + c * 8) = vl;
        }
#pragma unroll
        for (int t = 0; t < BN * 8 / 256; t++) {
            int idx = tid + t * 256;
            int n = idx >> 3, c = idx & 7;
            uint4 vh = __ldg(reinterpret_cast<const uint4*>(Whi + (size_t)n * KTOT + stage * 64) + c);
            uint4 vl = __ldg(reinterpret_cast<const uint4*>(Wlo + (size_t)n * KTOT + stage * 64) + c);
            *reinterpret_cast<uint4*>(sWh + n * RS + c * 8) = vh;
            *reinterpret_cast<uint4*>(sWl + n * RS + c * 8) = vl;
        }
        __syncthreads();

#pragma unroll
        for (int ks = 0; ks < 4; ks++) {
            const uint32_t koff = (uint32_t)(ks * 16 + (lane >> 4) * 8) * 2;
            uint32_t ah[2][4], al[2][4];
#pragma unroll
            for (int mt = 0; mt < 2; mt++) {
                uint32_t roff = (uint32_t)(wr * 32 + mt * 16 + (lane & 15)) * (RS * 2) + koff;
                ldsm4(ah[mt], sbAh + roff);
                ldsm4(al[mt], sbAl + roff);
            }
            uint32_t bh[NT][2], bl[NT][2];
#pragma unroll
            for (int g = 0; g < NT / 2; g++) {
                uint32_t roff = (uint32_t)(wc * (BN / 2) + g * 16 + (lane & 15)) * (RS * 2) + koff;
                uint32_t r[4];
                ldsm4(r, sbWh + roff);
                bh[2 * g][0] = r[0]; bh[2 * g][1] = r[2];
                bh[2 * g + 1][0] = r[1]; bh[2 * g + 1][1] = r[3];
                ldsm4(r, sbWl + roff);
                bl[2 * g][0] = r[0]; bl[2 * g][1] = r[2];
                bl[2 * g + 1][0] = r[1]; bl[2 * g + 1][1] = r[3];
            }
#pragma unroll
            for (int mt = 0; mt < 2; mt++)
#pragma unroll
                for (int nt = 0; nt < NT; nt++) {
                    mma16816(acc[mt][nt], ah[mt], bh[nt]);
                    mma16816(acc[mt][nt], al[mt], bh[nt]);
                    mma16816(acc[mt][nt], ah[mt], bl[nt]);
                }
        }
        __syncthreads();
    }

    if (MODE == 0) {
        // store h + fused BN column stats
#pragma unroll
        for (int nt = 0; nt < NT; nt++) {
            int col = wc * (BN / 2) + nt * 8 + (lane & 3) * 2;
            float2 bb = *reinterpret_cast<const float2*>(bias + col);
            float s0 = 0.f, s1 = 0.f, q0 = 0.f, q1 = 0.f;
#pragma unroll
            for (int mt = 0; mt < 2; mt++) {
                int r0 = rowBase + wr * 32 + mt * 16 + (lane >> 2);
                float v0 = acc[mt][nt][0] + bb.x, v1 = acc[mt][nt][1] + bb.y;
                float v2 = acc[mt][nt][2] + bb.x, v3 = acc[mt][nt][3] + bb.y;
                if (r0 < N_NODES) {
                    *reinterpret_cast<float2*>(out + (size_t)r0 * BN + col) = make_float2(v0, v1);
                    s0 += v0; s1 += v1; q0 += v0 * v0; q1 += v1 * v1;
                }
                if (r0 + 8 < N_NODES) {
                    *reinterpret_cast<float2*>(out + (size_t)(r0 + 8) * BN + col) = make_float2(v2, v3);
                    s0 += v2; s1 += v3; q0 += v2 * v2; q1 += v3 * v3;
                }
            }
#pragma unroll
            for (int off = 4; off < 32; off <<= 1) {
                s0 += __shfl_down_sync(0xffffffffu, s0, off);
                s1 += __shfl_down_sync(0xffffffffu, s1, off);
                q0 += __shfl_down_sync(0xffffffffu, q0, off);
                q1 += __shfl_down_sync(0xffffffffu, q1, off);
            }
            if ((lane >> 2) == 0) {
                atomicAdd(&ssum[col], s0); atomicAdd(&ssum[col + 1], s1);
                atomicAdd(&ssq[col], q0);  atomicAdd(&ssq[col + 1], q1);
            }
        }
        __syncthreads();
        if (tid < BN) {
            atomicAdd(&g_colsum[tid], ssum[tid]);
            atomicAdd(&g_colsq[tid], ssq[tid]);
        }
    } else {
        // fused log-softmax (BN == 64), reusing the dynamic smem
        float* hsm = reinterpret_cast<float*>(sm);
#pragma unroll
        for (int nt = 0; nt < NT; nt++) {
            int col = wc * 32 + nt * 8 + (lane & 3) * 2;
            float2 bb = *reinterpret_cast<const float2*>(bias + col);
#pragma unroll
            for (int mt = 0; mt < 2; mt++) {
                int rl = wr * 32 + mt * 16 + (lane >> 2);
                hsm[rl * 66 + col]       = acc[mt][nt][0] + bb.x;
                hsm[rl * 66 + col + 1]   = acc[mt][nt][1] + bb.y;
                hsm[(rl + 8) * 66 + col]     = acc[mt][nt][2] + bb.x;
                hsm[(rl + 8) * 66 + col + 1] = acc[mt][nt][3] + bb.y;
            }
        }
        __syncthreads();
        for (int i = 0; i < 16; i++) {
            int rl = warp * 16 + i;
            int row = rowBase + rl;
            if (row >= N_NODES) break;
            float a = hsm[rl * 66 + lane];
            float b = hsm[rl * 66 + lane + 32];
            float m = fmaxf(a, b);
#pragma unroll
            for (int o = 16; o > 0; o >>= 1) m = fmaxf(m, __shfl_xor_sync(0xffffffffu, m, o));
            float e = expf(a - m) + expf(b - m);
#pragma unroll
            for (int o = 16; o > 0; o >>= 1) e += __shfl_xor_sync(0xffffffffu, e, o);
            float l = m + logf(e);
            out[(size_t)row * D_OUT + lane] = a - l;
            out[(size_t)row * D_OUT + lane + 32] = b - l;
        }
    }
}

// ---------------- batch norm ------------------------------------------------
__global__ void k_bn_finalize(const float* __restrict__ gamma,
                              const float* __restrict__ beta) {
    int c = threadIdx.x;
    float mu = g_colsum[c] / (float)N_NODES;
    float var = g_colsq[c] / (float)N_NODES - mu * mu;
    float sc = gamma[c] * rsqrtf(var + BN_EPS);
    g_scale[c] = sc;
    g_shift[c] = beta[c] - mu * sc;
    g_colsum[c] = 0.f;   // self-restore for next layer / next replay
    g_colsq[c] = 0.f;
}

// read h, apply BN+ReLU, emit bf16 hi/lo self term into A cols 128..255
__global__ void k_bn_apply_relu(const float* __restrict__ h,
                                __nv_bfloat16* __restrict__ Ahi,
                                __nv_bfloat16* __restrict__ Alo) {
    int i4 = blockIdx.x * blockDim.x + threadIdx.x;
    const int total4 = N_NODES * D / 4;
    for (; i4 < total4; i4 += gridDim.x * blockDim.x) {
        int row = i4 >> 5;
        int c4 = (i4 & 31) * 4;
        float4 v = __ldg(reinterpret_cast<const float4*>(h) + i4);
        float a[4];
        a[0] = fmaxf(v.x * g_scale[c4 + 0] + g_shift[c4 + 0], 0.f);
        a[1] = fmaxf(v.y * g_scale[c4 + 1] + g_shift[c4 + 1], 0.f);
        a[2] = fmaxf(v.z * g_scale[c4 + 2] + g_shift[c4 + 2], 0.f);
        a[3] = fmaxf(v.w * g_scale[c4 + 3] + g_shift[c4 + 3], 0.f);
        __nv_bfloat16 hb[4], lb[4];
#pragma unroll
        for (int j = 0; j < 4; j++) bf16split(a[j], hb[j], lb[j]);
        size_t off = (size_t)row * KTOT + 128 + c4;
        *reinterpret_cast<uint2*>(Ahi + off) = *reinterpret_cast<uint2*>(hb);
        *reinterpret_cast<uint2*>(Alo + off) = *reinterpret_cast<uint2*>(lb);
    }
}

// ---------------- launch ----------------------------------------------------
extern "C" void kernel_launch(void* const* d_in, const int* in_sizes, int n_in,
                              void* d_out, int out_size) {
    const float* x   = (const float*)d_in[0];
    const int* ei    = (const int*)d_in[1];
    const float* Wl0 = (const float*)d_in[2];
    const float* Wr0 = (const float*)d_in[3];
    const float* b0  = (const float*)d_in[4];
    const float* g0  = (const float*)d_in[5];
    const float* be0 = (const float*)d_in[6];
    const float* Wl1 = (const float*)d_in[7];
    const float* Wr1 = (const float*)d_in[8];
    const float* b1  = (const float*)d_in[9];
    const float* g1  = (const float*)d_in[10];
    const float* be1 = (const float*)d_in[11];
    const float* Wl2 = (const float*)d_in[12];
    const float* Wr2 = (const float*)d_in[13];
    const float* b2  = (const float*)d_in[14];
    float* out = (float*)d_out;

    const int E = in_sizes[1] / 2;
    const int* src = ei;
    const int* dst = ei + E;

    float *h0, *h1;
    __nv_bfloat16 *Ahi, *Alo, *Whi, *Wlo;
    int *cnti, *rowptr, *cursor, *csr;
    cudaGetSymbolAddress((void**)&h0, g_h0);
    cudaGetSymbolAddress((void**)&h1, g_h1);
    cudaGetSymbolAddress((void**)&Ahi, g_Ahi);
    cudaGetSymbolAddress((void**)&Alo, g_Alo);
    cudaGetSymbolAddress((void**)&Whi, g_Whi);
    cudaGetSymbolAddress((void**)&Wlo, g_Wlo);
    cudaGetSymbolAddress((void**)&cnti, g_cnti);
    cudaGetSymbolAddress((void**)&rowptr, g_rowptr);
    cudaGetSymbolAddress((void**)&cursor, g_cursor);
    cudaGetSymbolAddress((void**)&csr, g_csr);

    constexpr int RS = 72;
    const int SMEM128 = (2 * 128 + 2 * 128) * RS * 2;  // 73728
    const int SMEM64  = (2 * 128 + 2 * 64) * RS * 2;   // 55296
    cudaFuncSetAttribute((const void*)k_mma_gemm<128, 0>, cudaFuncAttributeMaxDynamicSharedMemorySize, SMEM128);
    cudaFuncSetAttribute((const void*)k_mma_gemm<64, 1>,  cudaFuncAttributeMaxDynamicSharedMemorySize, SMEM64);

    const int aggBlocks  = (N_NODES * 32 + 255) / 256;
    const int gemmBlocks = (N_NODES + 127) / 128;

    __nv_bfloat16* W0h = Whi;               __nv_bfloat16* W0l = Wlo;
    __nv_bfloat16* W1h = Whi + 128 * KTOT;  __nv_bfloat16* W1l = Wlo + 128 * KTOT;
    __nv_bfloat16* W2h = Whi + 256 * KTOT;  __nv_bfloat16* W2l = Wlo + 256 * KTOT;

    // ---- CSR build + weight conversion ----
    k_zero_i<<<128, 256>>>(cnti, N_NODES);
    k_hist<<<1024, 256>>>(dst, E, cnti);
    k_scan<<<1, 1024>>>(cnti, rowptr, cursor);
    k_fill<<<1024, 256>>>(src, dst, E, cursor, csr);
    k_convert_w<<<(2 * 128 * KTOT + 64 * KTOT + 255) / 256, 256>>>(
        Wl0, Wr0, Wl1, Wr1, Wl2, Wr2, Whi, Wlo);

    // ---- layer 0 ----
    k_aggregate<true><<<aggBlocks, 256>>>(x, csr, rowptr, Ahi, Alo);
    k_mma_gemm<128, 0><<<gemmBlocks, 256, SMEM128>>>(Ahi, Alo, W0h, W0l, b0, h0);
    k_bn_finalize<<<1, 128>>>(g0, be0);
    k_bn_apply_relu<<<2048, 256>>>(h0, Ahi, Alo);

    // ---- layer 1 ----
    k_aggregate<false><<<aggBlocks, 256>>>(nullptr, csr, rowptr, Ahi, Alo);
    k_mma_gemm<128, 0><<<gemmBlocks, 256, SMEM128>>>(Ahi, Alo, W1h, W1l, b1, h1);
    k_bn_finalize<<<1, 128>>>(g1, be1);
    k_bn_apply_relu<<<2048, 256>>>(h1, Ahi, Alo);

    // ---- layer 2 ----
    k_aggregate<false><<<aggBlocks, 256>>>(nullptr, csr, rowptr, Ahi, Alo);
    k_mma_gemm<64, 1><<<gemmBlocks, 256, SMEM64>>>(Ahi, Alo, W2h, W2l, b2, out);
}

// round 7
// speedup vs baseline: 1.9728x; 1.0330x over previous
#include <cuda_runtime.h>
#include <cuda_bf16.h>
#include <cstdint>

#define N_NODES 50000
#define E_MAX   800000
#define D 128
#define KTOT 256
#define D_OUT 64
#define BN_EPS 1e-5f

// ---------------- scratch (device globals; no allocation allowed) ----------
__device__ __nv_bfloat16 g_Ahi[(size_t)N_NODES * KTOT];  // [mean | self] hi
__device__ __nv_bfloat16 g_Alo[(size_t)N_NODES * KTOT];  // [mean | self] lo
__device__ __nv_bfloat16 g_Whi[(size_t)(128 + 128 + 64) * KTOT];
__device__ __nv_bfloat16 g_Wlo[(size_t)(128 + 128 + 64) * KTOT];
__device__ float g_h0[(size_t)N_NODES * D];
__device__ float g_h1[(size_t)N_NODES * D];
__device__ int   g_cnti[N_NODES];
__device__ int   g_rowptr[N_NODES + 1];
__device__ int   g_cursor[N_NODES];
__device__ int   g_csr[E_MAX];
__device__ float g_colsum[D];
__device__ float g_colsq[D];
__device__ float g_scale[D];
__device__ float g_shift[D];

// ---------------- helpers ----------------------------------------------------
__device__ __forceinline__ uint32_t smem_u32(const void* p) {
    return (uint32_t)__cvta_generic_to_shared(p);
}

__device__ __forceinline__ void ldsm4(uint32_t* r, uint32_t a) {
    asm volatile("ldmatrix.sync.aligned.m8n8.x4.shared.b16 {%0,%1,%2,%3}, [%4];"
                 : "=r"(r[0]), "=r"(r[1]), "=r"(r[2]), "=r"(r[3]) : "r"(a));
}

__device__ __forceinline__ void mma16816(float* d, const uint32_t* a, const uint32_t* b) {
    asm volatile("mma.sync.aligned.m16n8k16.row.col.f32.bf16.bf16.f32 "
                 "{%0,%1,%2,%3}, {%4,%5,%6,%7}, {%8,%9}, {%0,%1,%2,%3};"
                 : "+f"(d[0]), "+f"(d[1]), "+f"(d[2]), "+f"(d[3])
                 : "r"(a[0]), "r"(a[1]), "r"(a[2]), "r"(a[3]), "r"(b[0]), "r"(b[1]));
}

__device__ __forceinline__ void bf16split(float v, __nv_bfloat16& hi, __nv_bfloat16& lo) {
    hi = __float2bfloat16(v);
    lo = __float2bfloat16(v - __bfloat162float(hi));
}

// ---------------- small utils ----------------------------------------------
__global__ void k_zero_i(int* __restrict__ p, int n) {
    int i = blockIdx.x * blockDim.x + threadIdx.x;
    for (; i < n; i += gridDim.x * blockDim.x) p[i] = 0;
}

// ---------------- CSR build (4-way unrolled for MLP) ------------------------
__global__ void k_hist(const int* __restrict__ dst, int E, int* __restrict__ cnt) {
    int i = blockIdx.x * blockDim.x + threadIdx.x;
    int stride = gridDim.x * blockDim.x;
    int nQuads = E >> 2;
    for (int q = i; q < nQuads; q += stride) {
        int4 d = __ldg(reinterpret_cast<const int4*>(dst) + q);
        atomicAdd(&cnt[d.x], 1);
        atomicAdd(&cnt[d.y], 1);
        atomicAdd(&cnt[d.z], 1);
        atomicAdd(&cnt[d.w], 1);
    }
    for (int e = nQuads * 4 + i; e < E; e += stride)
        atomicAdd(&cnt[__ldg(dst + e)], 1);
}

__global__ void k_scan(const int* __restrict__ cnt, int* __restrict__ row_ptr,
                       int* __restrict__ cursor) {
    constexpr int SEG = (N_NODES + 1023) / 1024;
    int t = threadIdx.x;
    int beg = t * SEG;
    int end = min(beg + SEG, N_NODES);
    int s = 0;
    for (int i = beg; i < end; i++) s += cnt[i];
    __shared__ int sh[1024];
    sh[t] = s;
    __syncthreads();
    for (int off = 1; off < 1024; off <<= 1) {
        int v = (t >= off) ? sh[t - off] : 0;
        __syncthreads();
        sh[t] += v;
        __syncthreads();
    }
    int pos = sh[t] - s;
    for (int i = beg; i < end; i++) {
        row_ptr[i] = pos;
        cursor[i]  = pos;
        pos += cnt[i];
    }
    if (beg < N_NODES && end == N_NODES) row_ptr[N_NODES] = pos;
}

__global__ void k_fill(const int* __restrict__ src, const int* __restrict__ dst,
                       int E, int* __restrict__ cursor, int* __restrict__ csr) {
    int i = blockIdx.x * blockDim.x + threadIdx.x;
    int stride = gridDim.x * blockDim.x;
    int nQuads = E >> 2;
    for (int q = i; q < nQuads; q += stride) {
        int4 d = __ldg(reinterpret_cast<const int4*>(dst) + q);
        int4 s = __ldg(reinterpret_cast<const int4*>(src) + q);
        int p0 = atomicAdd(&cursor[d.x], 1);
        int p1 = atomicAdd(&cursor[d.y], 1);
        int p2 = atomicAdd(&cursor[d.z], 1);
        int p3 = atomicAdd(&cursor[d.w], 1);
        csr[p0] = s.x; csr[p1] = s.y; csr[p2] = s.z; csr[p3] = s.w;
    }
    for (int e = nQuads * 4 + i; e < E; e += stride) {
        int d = __ldg(dst + e);
        int p = atomicAdd(&cursor[d], 1);
        csr[p] = __ldg(src + e);
    }
}

// ---------------- aggregation (+ optional fused BN+ReLU) --------------------
// One warp per node. Gathers fp32 features (optionally BN+ReLU'd on the fly),
// writes mean hi/lo (cols 0..127) and self hi/lo (cols 128..255).
template <bool APPLY_BN>
__global__ __launch_bounds__(256)
void k_aggregate(const float* __restrict__ xin, const int* __restrict__ csr,
                 const int* __restrict__ row_ptr,
                 __nv_bfloat16* __restrict__ Ahi, __nv_bfloat16* __restrict__ Alo) {
    int w = (blockIdx.x * blockDim.x + threadIdx.x) >> 5;
    if (w >= N_NODES) return;
    int lane = threadIdx.x & 31;

    float4 sc, sh;
    if (APPLY_BN) {
        sc = *reinterpret_cast<const float4*>(g_scale + lane * 4);
        sh = *reinterpret_cast<const float4*>(g_shift + lane * 4);
    }

    int beg = __ldg(row_ptr + w);
    int end = __ldg(row_ptr + w + 1);
    float4 a0 = make_float4(0.f, 0.f, 0.f, 0.f);
    float4 a1 = make_float4(0.f, 0.f, 0.f, 0.f);

    int i = beg;
    for (; i + 1 < end; i += 2) {
        int s0 = __ldg(csr + i);
        int s1 = __ldg(csr + i + 1);
        float4 v0 = __ldg(reinterpret_cast<const float4*>(xin + (size_t)s0 * D) + lane);
        float4 v1 = __ldg(reinterpret_cast<const float4*>(xin + (size_t)s1 * D) + lane);
        if (APPLY_BN) {
            v0.x = fmaxf(fmaf(v0.x, sc.x, sh.x), 0.f);
            v0.y = fmaxf(fmaf(v0.y, sc.y, sh.y), 0.f);
            v0.z = fmaxf(fmaf(v0.z, sc.z, sh.z), 0.f);
            v0.w = fmaxf(fmaf(v0.w, sc.w, sh.w), 0.f);
            v1.x = fmaxf(fmaf(v1.x, sc.x, sh.x), 0.f);
            v1.y = fmaxf(fmaf(v1.y, sc.y, sh.y), 0.f);
            v1.z = fmaxf(fmaf(v1.z, sc.z, sh.z), 0.f);
            v1.w = fmaxf(fmaf(v1.w, sc.w, sh.w), 0.f);
        }
        a0.x += v0.x; a0.y += v0.y; a0.z += v0.z; a0.w += v0.w;
        a1.x += v1.x; a1.y += v1.y; a1.z += v1.z; a1.w += v1.w;
    }
    if (i < end) {
        int s0 = __ldg(csr + i);
        float4 v0 = __ldg(reinterpret_cast<const float4*>(xin + (size_t)s0 * D) + lane);
        if (APPLY_BN) {
            v0.x = fmaxf(fmaf(v0.x, sc.x, sh.x), 0.f);
            v0.y = fmaxf(fmaf(v0.y, sc.y, sh.y), 0.f);
            v0.z = fmaxf(fmaf(v0.z, sc.z, sh.z), 0.f);
            v0.w = fmaxf(fmaf(v0.w, sc.w, sh.w), 0.f);
        }
        a0.x += v0.x; a0.y += v0.y; a0.z += v0.z; a0.w += v0.w;
    }

    float inv = 1.f / (float)max(end - beg, 1);
    float v[4] = {(a0.x + a1.x) * inv, (a0.y + a1.y) * inv,
                  (a0.z + a1.z) * inv, (a0.w + a1.w) * inv};
    __nv_bfloat16 hb[4], lb[4];
#pragma unroll
    for (int j = 0; j < 4; j++) bf16split(v[j], hb[j], lb[j]);
    size_t off = (size_t)w * KTOT + lane * 4;
    *reinterpret_cast<uint2*>(Ahi + off) = *reinterpret_cast<uint2*>(hb);
    *reinterpret_cast<uint2*>(Alo + off) = *reinterpret_cast<uint2*>(lb);

    // self term (cols 128..255): own row, BN'd if requested
    float4 xv = __ldg(reinterpret_cast<const float4*>(xin + (size_t)w * D) + lane);
    if (APPLY_BN) {
        xv.x = fmaxf(fmaf(xv.x, sc.x, sh.x), 0.f);
        xv.y = fmaxf(fmaf(xv.y, sc.y, sh.y), 0.f);
        xv.z = fmaxf(fmaf(xv.z, sc.z, sh.z), 0.f);
        xv.w = fmaxf(fmaf(xv.w, sc.w, sh.w), 0.f);
    }
    float s[4] = {xv.x, xv.y, xv.z, xv.w};
    __nv_bfloat16 shb[4], slb[4];
#pragma unroll
    for (int j = 0; j < 4; j++) bf16split(s[j], shb[j], slb[j]);
    *reinterpret_cast<uint2*>(Ahi + off + 128) = *reinterpret_cast<uint2*>(shb);
    *reinterpret_cast<uint2*>(Alo + off + 128) = *reinterpret_cast<uint2*>(slb);
}

// ---------------- weight convert: all 3 layers in one launch ----------------
__global__ void k_convert_w(const float* __restrict__ Wl0, const float* __restrict__ Wr0,
                            const float* __restrict__ Wl1, const float* __restrict__ Wr1,
                            const float* __restrict__ Wl2, const float* __restrict__ Wr2,
                            __nv_bfloat16* __restrict__ Whi, __nv_bfloat16* __restrict__ Wlo) {
    int idx = blockIdx.x * blockDim.x + threadIdx.x;
    const int T01 = 128 * KTOT;
    const int total = 2 * T01 + 64 * KTOT;
    if (idx >= total) return;
    const float *Wl, *Wr;
    int local, BN;
    if (idx < T01) { Wl = Wl0; Wr = Wr0; local = idx; BN = 128; }
    else if (idx < 2 * T01) { Wl = Wl1; Wr = Wr1; local = idx - T01; BN = 128; }
    else { Wl = Wl2; Wr = Wr2; local = idx - 2 * T01; BN = 64; }
    int n = local >> 8;
    int k = local & 255;
    float v = (k < 128) ? __ldg(Wl + (size_t)k * BN + n)
                        : __ldg(Wr + (size_t)(k - 128) * BN + n);
    __nv_bfloat16 h, l;
    bf16split(v, h, l);
    Whi[idx] = h;
    Wlo[idx] = l;
}

// ---------------- HMMA fused SAGE GEMM --------------------------------------
// out[128 x BN] = A[128 x 256] @ W^T (+bias); acc = Ah*Wh + Al*Wh + Ah*Wl.
// MODE 0: store h + fused BN column stats.  MODE 1: fused log-softmax to out.
template <int BN, int MODE>
__global__ __launch_bounds__(256)
void k_mma_gemm(const __nv_bfloat16* __restrict__ Ahi, const __nv_bfloat16* __restrict__ Alo,
                const __nv_bfloat16* __restrict__ Whi, const __nv_bfloat16* __restrict__ Wlo,
                const float* __restrict__ bias, float* __restrict__ out) {
    constexpr int RS = 72;           // bf16 per smem row (64 data + 8 pad = 144B)
    constexpr int NT = BN / 16;      // n-tiles per warp (8 or 4)
    extern __shared__ __nv_bfloat16 sm[];
    __nv_bfloat16* sAh = sm;
    __nv_bfloat16* sAl = sm + 128 * RS;
    __nv_bfloat16* sWh = sm + 2 * 128 * RS;
    __nv_bfloat16* sWl = sWh + BN * RS;

    __shared__ float ssum[128];
    __shared__ float ssq[128];

    const int tid = threadIdx.x;
    const int lane = tid & 31;
    const int warp = tid >> 5;
    const int wr = warp & 3;
    const int wc = warp >> 2;
    const int rowBase = blockIdx.x * 128;

    if (MODE == 0 && tid < BN) { ssum[tid] = 0.f; ssq[tid] = 0.f; }

    const uint32_t sbAh = smem_u32(sAh);
    const uint32_t sbAl = smem_u32(sAl);
    const uint32_t sbWh = smem_u32(sWh);
    const uint32_t sbWl = smem_u32(sWl);

    float acc[2][NT][4];
#pragma unroll
    for (int mt = 0; mt < 2; mt++)
#pragma unroll
        for (int nt = 0; nt < NT; nt++)
#pragma unroll
            for (int j = 0; j < 4; j++) acc[mt][nt][j] = 0.f;

    for (int stage = 0; stage < 4; stage++) {
#pragma unroll
        for (int t = 0; t < 4; t++) {
            int idx = tid + t * 256;
            int r = idx >> 3, c = idx & 7;
            int row = rowBase + r;
            uint4 vh = make_uint4(0, 0, 0, 0), vl = make_uint4(0, 0, 0, 0);
            if (row < N_NODES) {
                vh = __ldg(reinterpret_cast<const uint4*>(Ahi + (size_t)row * KTOT + stage * 64) + c);
                vl = __ldg(reinterpret_cast<const uint4*>(Alo + (size_t)row * KTOT + stage * 64) + c);
            }
            *reinterpret_cast<uint4*>(sAh + r * RS + c * 8) = vh;
            *reinterpret_cast<uint4*>(sAl + r * RS + c * 8) = vl;
        }
#pragma unroll
        for (int t = 0; t < BN * 8 / 256; t++) {
            int idx = tid + t * 256;
            int n = idx >> 3, c = idx & 7;
            uint4 vh = __ldg(reinterpret_cast<const uint4*>(Whi + (size_t)n * KTOT + stage * 64) + c);
            uint4 vl = __ldg(reinterpret_cast<const uint4*>(Wlo + (size_t)n * KTOT + stage * 64) + c);
            *reinterpret_cast<uint4*>(sWh + n * RS + c * 8) = vh;
            *reinterpret_cast<uint4*>(sWl + n * RS + c * 8) = vl;
        }
        __syncthreads();

#pragma unroll
        for (int ks = 0; ks < 4; ks++) {
            const uint32_t koff = (uint32_t)(ks * 16 + (lane >> 4) * 8) * 2;
            uint32_t ah[2][4], al[2][4];
#pragma unroll
            for (int mt = 0; mt < 2; mt++) {
                uint32_t roff = (uint32_t)(wr * 32 + mt * 16 + (lane & 15)) * (RS * 2) + koff;
                ldsm4(ah[mt], sbAh + roff);
                ldsm4(al[mt], sbAl + roff);
            }
            uint32_t bh[NT][2], bl[NT][2];
#pragma unroll
            for (int g = 0; g < NT / 2; g++) {
                uint32_t roff = (uint32_t)(wc * (BN / 2) + g * 16 + (lane & 15)) * (RS * 2) + koff;
                uint32_t r[4];
                ldsm4(r, sbWh + roff);
                bh[2 * g][0] = r[0]; bh[2 * g][1] = r[2];
                bh[2 * g + 1][0] = r[1]; bh[2 * g + 1][1] = r[3];
                ldsm4(r, sbWl + roff);
                bl[2 * g][0] = r[0]; bl[2 * g][1] = r[2];
                bl[2 * g + 1][0] = r[1]; bl[2 * g + 1][1] = r[3];
            }
#pragma unroll
            for (int mt = 0; mt < 2; mt++)
#pragma unroll
                for (int nt = 0; nt < NT; nt++) {
                    mma16816(acc[mt][nt], ah[mt], bh[nt]);
                    mma16816(acc[mt][nt], al[mt], bh[nt]);
                    mma16816(acc[mt][nt], ah[mt], bl[nt]);
                }
        }
        __syncthreads();
    }

    if (MODE == 0) {
        // store h + fused BN column stats
#pragma unroll
        for (int nt = 0; nt < NT; nt++) {
            int col = wc * (BN / 2) + nt * 8 + (lane & 3) * 2;
            float2 bb = *reinterpret_cast<const float2*>(bias + col);
            float s0 = 0.f, s1 = 0.f, q0 = 0.f, q1 = 0.f;
#pragma unroll
            for (int mt = 0; mt < 2; mt++) {
                int r0 = rowBase + wr * 32 + mt * 16 + (lane >> 2);
                float v0 = acc[mt][nt][0] + bb.x, v1 = acc[mt][nt][1] + bb.y;
                float v2 = acc[mt][nt][2] + bb.x, v3 = acc[mt][nt][3] + bb.y;
                if (r0 < N_NODES) {
                    *reinterpret_cast<float2*>(out + (size_t)r0 * BN + col) = make_float2(v0, v1);
                    s0 += v0; s1 += v1; q0 += v0 * v0; q1 += v1 * v1;
                }
                if (r0 + 8 < N_NODES) {
                    *reinterpret_cast<float2*>(out + (size_t)(r0 + 8) * BN + col) = make_float2(v2, v3);
                    s0 += v2; s1 += v3; q0 += v2 * v2; q1 += v3 * v3;
                }
            }
#pragma unroll
            for (int off = 4; off < 32; off <<= 1) {
                s0 += __shfl_down_sync(0xffffffffu, s0, off);
                s1 += __shfl_down_sync(0xffffffffu, s1, off);
                q0 += __shfl_down_sync(0xffffffffu, q0, off);
                q1 += __shfl_down_sync(0xffffffffu, q1, off);
            }
            if ((lane >> 2) == 0) {
                atomicAdd(&ssum[col], s0); atomicAdd(&ssum[col + 1], s1);
                atomicAdd(&ssq[col], q0);  atomicAdd(&ssq[col + 1], q1);
            }
        }
        __syncthreads();
        if (tid < BN) {
            atomicAdd(&g_colsum[tid], ssum[tid]);
            atomicAdd(&g_colsq[tid], ssq[tid]);
        }
    } else {
        // fused log-softmax (BN == 64), reusing the dynamic smem
        float* hsm = reinterpret_cast<float*>(sm);
#pragma unroll
        for (int nt = 0; nt < NT; nt++) {
            int col = wc * 32 + nt * 8 + (lane & 3) * 2;
            float2 bb = *reinterpret_cast<const float2*>(bias + col);
#pragma unroll
            for (int mt = 0; mt < 2; mt++) {
                int rl = wr * 32 + mt * 16 + (lane >> 2);
                hsm[rl * 66 + col]       = acc[mt][nt][0] + bb.x;
                hsm[rl * 66 + col + 1]   = acc[mt][nt][1] + bb.y;
                hsm[(rl + 8) * 66 + col]     = acc[mt][nt][2] + bb.x;
                hsm[(rl + 8) * 66 + col + 1] = acc[mt][nt][3] + bb.y;
            }
        }
        __syncthreads();
        for (int i = 0; i < 16; i++) {
            int rl = warp * 16 + i;
            int row = rowBase + rl;
            if (row >= N_NODES) break;
            float a = hsm[rl * 66 + lane];
            float b = hsm[rl * 66 + lane + 32];
            float m = fmaxf(a, b);
#pragma unroll
            for (int o = 16; o > 0; o >>= 1) m = fmaxf(m, __shfl_xor_sync(0xffffffffu, m, o));
            float e = expf(a - m) + expf(b - m);
#pragma unroll
            for (int o = 16; o > 0; o >>= 1) e += __shfl_xor_sync(0xffffffffu, e, o);
            float l = m + logf(e);
            out[(size_t)row * D_OUT + lane] = a - l;
            out[(size_t)row * D_OUT + lane + 32] = b - l;
        }
    }
}

// ---------------- batch norm finalize ---------------------------------------
__global__ void k_bn_finalize(const float* __restrict__ gamma,
                              const float* __restrict__ beta) {
    int c = threadIdx.x;
    float mu = g_colsum[c] / (float)N_NODES;
    float var = g_colsq[c] / (float)N_NODES - mu * mu;
    float sc = gamma[c] * rsqrtf(var + BN_EPS);
    g_scale[c] = sc;
    g_shift[c] = beta[c] - mu * sc;
    g_colsum[c] = 0.f;   // self-restore for next layer / next replay
    g_colsq[c] = 0.f;
}

// ---------------- launch ----------------------------------------------------
extern "C" void kernel_launch(void* const* d_in, const int* in_sizes, int n_in,
                              void* d_out, int out_size) {
    const float* x   = (const float*)d_in[0];
    const int* ei    = (const int*)d_in[1];
    const float* Wl0 = (const float*)d_in[2];
    const float* Wr0 = (const float*)d_in[3];
    const float* b0  = (const float*)d_in[4];
    const float* g0  = (const float*)d_in[5];
    const float* be0 = (const float*)d_in[6];
    const float* Wl1 = (const float*)d_in[7];
    const float* Wr1 = (const float*)d_in[8];
    const float* b1  = (const float*)d_in[9];
    const float* g1  = (const float*)d_in[10];
    const float* be1 = (const float*)d_in[11];
    const float* Wl2 = (const float*)d_in[12];
    const float* Wr2 = (const float*)d_in[13];
    const float* b2  = (const float*)d_in[14];
    float* out = (float*)d_out;

    const int E = in_sizes[1] / 2;
    const int* src = ei;
    const int* dst = ei + E;

    float *h0, *h1;
    __nv_bfloat16 *Ahi, *Alo, *Whi, *Wlo;
    int *cnti, *rowptr, *cursor, *csr;
    cudaGetSymbolAddress((void**)&h0, g_h0);
    cudaGetSymbolAddress((void**)&h1, g_h1);
    cudaGetSymbolAddress((void**)&Ahi, g_Ahi);
    cudaGetSymbolAddress((void**)&Alo, g_Alo);
    cudaGetSymbolAddress((void**)&Whi, g_Whi);
    cudaGetSymbolAddress((void**)&Wlo, g_Wlo);
    cudaGetSymbolAddress((void**)&cnti, g_cnti);
    cudaGetSymbolAddress((void**)&rowptr, g_rowptr);
    cudaGetSymbolAddress((void**)&cursor, g_cursor);
    cudaGetSymbolAddress((void**)&csr, g_csr);

    constexpr int RS = 72;
    const int SMEM128 = (2 * 128 + 2 * 128) * RS * 2;  // 73728
    const int SMEM64  = (2 * 128 + 2 * 64) * RS * 2;   // 55296
    cudaFuncSetAttribute((const void*)k_mma_gemm<128, 0>, cudaFuncAttributeMaxDynamicSharedMemorySize, SMEM128);
    cudaFuncSetAttribute((const void*)k_mma_gemm<64, 1>,  cudaFuncAttributeMaxDynamicSharedMemorySize, SMEM64);

    const int aggBlocks  = (N_NODES * 32 + 255) / 256;
    const int gemmBlocks = (N_NODES + 127) / 128;

    __nv_bfloat16* W0h = Whi;               __nv_bfloat16* W0l = Wlo;
    __nv_bfloat16* W1h = Whi + 128 * KTOT;  __nv_bfloat16* W1l = Wlo + 128 * KTOT;
    __nv_bfloat16* W2h = Whi + 256 * KTOT;  __nv_bfloat16* W2l = Wlo + 256 * KTOT;

    // ---- CSR build + weight conversion ----
    k_zero_i<<<128, 256>>>(cnti, N_NODES);
    k_hist<<<512, 256>>>(dst, E, cnti);
    k_scan<<<1, 1024>>>(cnti, rowptr, cursor);
    k_fill<<<512, 256>>>(src, dst, E, cursor, csr);
    k_convert_w<<<(2 * 128 * KTOT + 64 * KTOT + 255) / 256, 256>>>(
        Wl0, Wr0, Wl1, Wr1, Wl2, Wr2, Whi, Wlo);

    // ---- layer 0 ----
    k_aggregate<false><<<aggBlocks, 256>>>(x, csr, rowptr, Ahi, Alo);
    k_mma_gemm<128, 0><<<gemmBlocks, 256, SMEM128>>>(Ahi, Alo, W0h, W0l, b0, h0);
    k_bn_finalize<<<1, 128>>>(g0, be0);

    // ---- layer 1 (BN+ReLU fused into aggregation) ----
    k_aggregate<true><<<aggBlocks, 256>>>(h0, csr, rowptr, Ahi, Alo);
    k_mma_gemm<128, 0><<<gemmBlocks, 256, SMEM128>>>(Ahi, Alo, W1h, W1l, b1, h1);
    k_bn_finalize<<<1, 128>>>(g1, be1);

    // ---- layer 2 (BN+ReLU fused into aggregation, log-softmax in GEMM) ----
    k_aggregate<true><<<aggBlocks, 256>>>(h1, csr, rowptr, Ahi, Alo);
    k_mma_gemm<64, 1><<<gemmBlocks, 256, SMEM64>>>(Ahi, Alo, W2h, W2l, b2, out);
}

// round 8
// speedup vs baseline: 2.0922x; 1.0605x over previous
#include <cuda_runtime.h>
#include <cuda_bf16.h>
#include <cstdint>

#define N_NODES 50000
#define E_MAX   800000
#define D 128
#define KTOT 256
#define D_OUT 64
#define BN_EPS 1e-5f
#define WTOT (2 * 128 * 256 + 128 * 128)

// ---------------- scratch (device globals; no allocation allowed) ----------
__device__ __nv_bfloat16 g_Ahi[(size_t)N_NODES * KTOT];  // [mean | self] hi
__device__ __nv_bfloat16 g_Alo[(size_t)N_NODES * KTOT];  // [mean | self] lo
__device__ __nv_bfloat16 g_Whi[WTOT];
__device__ __nv_bfloat16 g_Wlo[WTOT];
__device__ float g_h0[(size_t)N_NODES * D];   // layer0 out; later reused for [z2|s2]
__device__ float g_h1[(size_t)N_NODES * D];
__device__ int   g_cnti[N_NODES];
__device__ int   g_rowptr[N_NODES + 1];
__device__ int   g_rank[E_MAX];
__device__ int   g_csr[E_MAX];
__device__ float g_sum0[D];
__device__ float g_sq0[D];
__device__ float g_sum1[D];
__device__ float g_sq1[D];

// ---------------- helpers ----------------------------------------------------
__device__ __forceinline__ uint32_t smem_u32(const void* p) {
    return (uint32_t)__cvta_generic_to_shared(p);
}

__device__ __forceinline__ void ldsm4(uint32_t* r, uint32_t a) {
    asm volatile("ldmatrix.sync.aligned.m8n8.x4.shared.b16 {%0,%1,%2,%3}, [%4];"
                 : "=r"(r[0]), "=r"(r[1]), "=r"(r[2]), "=r"(r[3]) : "r"(a));
}

__device__ __forceinline__ void mma16816(float* d, const uint32_t* a, const uint32_t* b) {
    asm volatile("mma.sync.aligned.m16n8k16.row.col.f32.bf16.bf16.f32 "
                 "{%0,%1,%2,%3}, {%4,%5,%6,%7}, {%8,%9}, {%0,%1,%2,%3};"
                 : "+f"(d[0]), "+f"(d[1]), "+f"(d[2]), "+f"(d[3])
                 : "r"(a[0]), "r"(a[1]), "r"(a[2]), "r"(a[3]), "r"(b[0]), "r"(b[1]));
}

__device__ __forceinline__ void bf16split(float v, __nv_bfloat16& hi, __nv_bfloat16& lo) {
    hi = __float2bfloat16(v);
    lo = __float2bfloat16(v - __bfloat162float(hi));
}

// ---------------- prep: weight convert + degree histogram + ranks -----------
__global__ void k_prep(const int* __restrict__ dst, int E,
                       int* __restrict__ cnt, int* __restrict__ rank,
                       const float* __restrict__ Wl0, const float* __restrict__ Wr0,
                       const float* __restrict__ Wl1, const float* __restrict__ Wr1,
                       const float* __restrict__ Wl2, const float* __restrict__ Wr2,
                       __nv_bfloat16* __restrict__ Whi, __nv_bfloat16* __restrict__ Wlo) {
    int idx = blockIdx.x * blockDim.x + threadIdx.x;
    if (idx < WTOT) {
        const int T01 = 128 * 256;
        float v;
        if (idx < T01) {
            int n = idx >> 8, k = idx & 255;
            v = (k < 128) ? __ldg(Wl0 + k * 128 + n) : __ldg(Wr0 + (k - 128) * 128 + n);
        } else if (idx < 2 * T01) {
            int l = idx - T01;
            int n = l >> 8, k = l & 255;
            v = (k < 128) ? __ldg(Wl1 + k * 128 + n) : __ldg(Wr1 + (k - 128) * 128 + n);
        } else {
            int l = idx - 2 * T01;
            int n = l >> 7, k = l & 127;
            v = (n < 64) ? __ldg(Wl2 + k * 64 + n) : __ldg(Wr2 + k * 64 + (n - 64));
        }
        __nv_bfloat16 h, lo;
        bf16split(v, h, lo);
        Whi[idx] = h;
        Wlo[idx] = lo;
    }
    int stride = gridDim.x * blockDim.x;
    int nQ = E >> 2;
    for (int q = idx; q < nQ; q += stride) {
        int4 d = __ldg(reinterpret_cast<const int4*>(dst) + q);
        int4 r;
        r.x = atomicAdd(&cnt[d.x], 1);
        r.y = atomicAdd(&cnt[d.y], 1);
        r.z = atomicAdd(&cnt[d.z], 1);
        r.w = atomicAdd(&cnt[d.w], 1);
        *(reinterpret_cast<int4*>(rank) + q) = r;
    }
    for (int e = nQ * 4 + idx; e < E; e += stride)
        rank[e] = atomicAdd(&cnt[__ldg(dst + e)], 1);
}

// single block, 1024 threads: exclusive scan; self-zeroes cnt for next replay
__global__ void k_scan(int* __restrict__ cnt, int* __restrict__ row_ptr) {
    constexpr int SEG = (N_NODES + 1023) / 1024;
    int t = threadIdx.x;
    int beg = t * SEG;
    int end = min(beg + SEG, N_NODES);
    int s = 0;
    for (int i = beg; i < end; i++) s += cnt[i];
    __shared__ int sh[1024];
    sh[t] = s;
    __syncthreads();
    for (int off = 1; off < 1024; off <<= 1) {
        int v = (t >= off) ? sh[t - off] : 0;
        __syncthreads();
        sh[t] += v;
        __syncthreads();
    }
    int pos = sh[t] - s;
    for (int i = beg; i < end; i++) {
        int c = cnt[i];
        row_ptr[i] = pos;
        pos += c;
        cnt[i] = 0;
    }
    if (beg < N_NODES && end == N_NODES) row_ptr[N_NODES] = pos;
}

// atomic-free fill using precomputed ranks
__global__ void k_fill(const int* __restrict__ src, const int* __restrict__ dst,
                       int E, const int* __restrict__ rank,
                       const int* __restrict__ row_ptr, int* __restrict__ csr) {
    int i = blockIdx.x * blockDim.x + threadIdx.x;
    int stride = gridDim.x * blockDim.x;
    int nQ = E >> 2;
    for (int q = i; q < nQ; q += stride) {
        int4 d = __ldg(reinterpret_cast<const int4*>(dst) + q);
        int4 s = __ldg(reinterpret_cast<const int4*>(src) + q);
        int4 r = __ldg(reinterpret_cast<const int4*>(rank) + q);
        csr[__ldg(row_ptr + d.x) + r.x] = s.x;
        csr[__ldg(row_ptr + d.y) + r.y] = s.y;
        csr[__ldg(row_ptr + d.z) + r.z] = s.z;
        csr[__ldg(row_ptr + d.w) + r.w] = s.w;
    }
    for (int e = nQ * 4 + i; e < E; e += stride)
        csr[__ldg(row_ptr + __ldg(dst + e)) + __ldg(rank + e)] = __ldg(src + e);
}

// ---------------- aggregation (+ optional inline BN+ReLU) -------------------
// One warp per node; writes mean hi/lo (cols 0..127) + self hi/lo (128..255).
// Block 0 zeroes the NEXT layer's stats buffers.
template <bool APPLY_BN>
__global__ __launch_bounds__(256)
void k_aggregate(const float* __restrict__ xin, const int* __restrict__ csr,
                 const int* __restrict__ row_ptr,
                 __nv_bfloat16* __restrict__ Ahi, __nv_bfloat16* __restrict__ Alo,
                 const float* __restrict__ stSum, const float* __restrict__ stSq,
                 const float* __restrict__ gamma, const float* __restrict__ beta,
                 float* __restrict__ zSum, float* __restrict__ zSq) {
    __shared__ float ssc[128], ssh[128];
    int tid = threadIdx.x;
    if (blockIdx.x == 0 && tid < 128) { zSum[tid] = 0.f; zSq[tid] = 0.f; }
    if (APPLY_BN) {
        if (tid < 128) {
            float mu = __ldg(stSum + tid) / (float)N_NODES;
            float var = __ldg(stSq + tid) / (float)N_NODES - mu * mu;
            float sc = __ldg(gamma + tid) * rsqrtf(var + BN_EPS);
            ssc[tid] = sc;
            ssh[tid] = __ldg(beta + tid) - mu * sc;
        }
        __syncthreads();
    }

    int w = (blockIdx.x * blockDim.x + tid) >> 5;
    if (w >= N_NODES) return;
    int lane = tid & 31;

    float4 sc, sh;
    if (APPLY_BN) {
        sc = *reinterpret_cast<const float4*>(ssc + lane * 4);
        sh = *reinterpret_cast<const float4*>(ssh + lane * 4);
    }

    int beg = __ldg(row_ptr + w);
    int end = __ldg(row_ptr + w + 1);
    float4 a0 = make_float4(0.f, 0.f, 0.f, 0.f);
    float4 a1 = make_float4(0.f, 0.f, 0.f, 0.f);

    int i = beg;
    for (; i + 1 < end; i += 2) {
        int s0 = __ldg(csr + i);
        int s1 = __ldg(csr + i + 1);
        float4 v0 = __ldg(reinterpret_cast<const float4*>(xin + (size_t)s0 * D) + lane);
        float4 v1 = __ldg(reinterpret_cast<const float4*>(xin + (size_t)s1 * D) + lane);
        if (APPLY_BN) {
            v0.x = fmaxf(fmaf(v0.x, sc.x, sh.x), 0.f);
            v0.y = fmaxf(fmaf(v0.y, sc.y, sh.y), 0.f);
            v0.z = fmaxf(fmaf(v0.z, sc.z, sh.z), 0.f);
            v0.w = fmaxf(fmaf(v0.w, sc.w, sh.w), 0.f);
            v1.x = fmaxf(fmaf(v1.x, sc.x, sh.x), 0.f);
            v1.y = fmaxf(fmaf(v1.y, sc.y, sh.y), 0.f);
            v1.z = fmaxf(fmaf(v1.z, sc.z, sh.z), 0.f);
            v1.w = fmaxf(fmaf(v1.w, sc.w, sh.w), 0.f);
        }
        a0.x += v0.x; a0.y += v0.y; a0.z += v0.z; a0.w += v0.w;
        a1.x += v1.x; a1.y += v1.y; a1.z += v1.z; a1.w += v1.w;
    }
    if (i < end) {
        int s0 = __ldg(csr + i);
        float4 v0 = __ldg(reinterpret_cast<const float4*>(xin + (size_t)s0 * D) + lane);
        if (APPLY_BN) {
            v0.x = fmaxf(fmaf(v0.x, sc.x, sh.x), 0.f);
            v0.y = fmaxf(fmaf(v0.y, sc.y, sh.y), 0.f);
            v0.z = fmaxf(fmaf(v0.z, sc.z, sh.z), 0.f);
            v0.w = fmaxf(fmaf(v0.w, sc.w, sh.w), 0.f);
        }
        a0.x += v0.x; a0.y += v0.y; a0.z += v0.z; a0.w += v0.w;
    }

    float inv = 1.f / (float)max(end - beg, 1);
    float v[4] = {(a0.x + a1.x) * inv, (a0.y + a1.y) * inv,
                  (a0.z + a1.z) * inv, (a0.w + a1.w) * inv};
    __nv_bfloat16 hb[4], lb[4];
#pragma unroll
    for (int j = 0; j < 4; j++) bf16split(v[j], hb[j], lb[j]);
    size_t off = (size_t)w * KTOT + lane * 4;
    *reinterpret_cast<uint2*>(Ahi + off) = *reinterpret_cast<uint2*>(hb);
    *reinterpret_cast<uint2*>(Alo + off) = *reinterpret_cast<uint2*>(lb);

    // self term (cols 128..255)
    float4 xv = __ldg(reinterpret_cast<const float4*>(xin + (size_t)w * D) + lane);
    if (APPLY_BN) {
        xv.x = fmaxf(fmaf(xv.x, sc.x, sh.x), 0.f);
        xv.y = fmaxf(fmaf(xv.y, sc.y, sh.y), 0.f);
        xv.z = fmaxf(fmaf(xv.z, sc.z, sh.z), 0.f);
        xv.w = fmaxf(fmaf(xv.w, sc.w, sh.w), 0.f);
    }
    float s[4] = {xv.x, xv.y, xv.z, xv.w};
    __nv_bfloat16 shb[4], slb[4];
#pragma unroll
    for (int j = 0; j < 4; j++) bf16split(s[j], shb[j], slb[j]);
    *reinterpret_cast<uint2*>(Ahi + off + 128) = *reinterpret_cast<uint2*>(shb);
    *reinterpret_cast<uint2*>(Alo + off + 128) = *reinterpret_cast<uint2*>(slb);
}

// ---------------- HMMA GEMM layers 0/1 (K=256, N=128) -----------------------
// out = A @ W^T + b; fused BN column-stat accumulation into stSum/stSq.
__global__ __launch_bounds__(256)
void k_mma_gemm(const __nv_bfloat16* __restrict__ Ahi, const __nv_bfloat16* __restrict__ Alo,
                const __nv_bfloat16* __restrict__ Whi, const __nv_bfloat16* __restrict__ Wlo,
                const float* __restrict__ bias, float* __restrict__ out,
                float* __restrict__ stSum, float* __restrict__ stSq) {
    constexpr int BN = 128;
    constexpr int RS = 72;
    constexpr int NT = 8;
    extern __shared__ __nv_bfloat16 sm[];
    __nv_bfloat16* sAh = sm;
    __nv_bfloat16* sAl = sm + 128 * RS;
    __nv_bfloat16* sWh = sm + 2 * 128 * RS;
    __nv_bfloat16* sWl = sWh + BN * RS;

    __shared__ float ssum[128];
    __shared__ float ssq[128];

    const int tid = threadIdx.x;
    const int lane = tid & 31;
    const int warp = tid >> 5;
    const int wr = warp & 3;
    const int wc = warp >> 2;
    const int rowBase = blockIdx.x * 128;

    if (tid < BN) { ssum[tid] = 0.f; ssq[tid] = 0.f; }

    const uint32_t sbAh = smem_u32(sAh);
    const uint32_t sbAl = smem_u32(sAl);
    const uint32_t sbWh = smem_u32(sWh);
    const uint32_t sbWl = smem_u32(sWl);

    float acc[2][NT][4];
#pragma unroll
    for (int mt = 0; mt < 2; mt++)
#pragma unroll
        for (int nt = 0; nt < NT; nt++)
#pragma unroll
            for (int j = 0; j < 4; j++) acc[mt][nt][j] = 0.f;

    for (int stage = 0; stage < 4; stage++) {
#pragma unroll
        for (int t = 0; t < 4; t++) {
            int idx = tid + t * 256;
            int r = idx >> 3, c = idx & 7;
            int row = rowBase + r;
            uint4 vh = make_uint4(0, 0, 0, 0), vl = make_uint4(0, 0, 0, 0);
            if (row < N_NODES) {
                vh = __ldg(reinterpret_cast<const uint4*>(Ahi + (size_t)row * KTOT + stage * 64) + c);
                vl = __ldg(reinterpret_cast<const uint4*>(Alo + (size_t)row * KTOT + stage * 64) + c);
            }
            *reinterpret_cast<uint4*>(sAh + r * RS + c * 8) = vh;
            *reinterpret_cast<uint4*>(sAl + r * RS + c * 8) = vl;
        }
#pragma unroll
        for (int t = 0; t < 4; t++) {
            int idx = tid + t * 256;
            int n = idx >> 3, c = idx & 7;
            uint4 vh = __ldg(reinterpret_cast<const uint4*>(Whi + (size_t)n * KTOT + stage * 64) + c);
            uint4 vl = __ldg(reinterpret_cast<const uint4*>(Wlo + (size_t)n * KTOT + stage * 64) + c);
            *reinterpret_cast<uint4*>(sWh + n * RS + c * 8) = vh;
            *reinterpret_cast<uint4*>(sWl + n * RS + c * 8) = vl;
        }
        __syncthreads();

#pragma unroll
        for (int ks = 0; ks < 4; ks++) {
            const uint32_t koff = (uint32_t)(ks * 16 + (lane >> 4) * 8) * 2;
            uint32_t ah[2][4], al[2][4];
#pragma unroll
            for (int mt = 0; mt < 2; mt++) {
                uint32_t roff = (uint32_t)(wr * 32 + mt * 16 + (lane & 15)) * (RS * 2) + koff;
                ldsm4(ah[mt], sbAh + roff);
                ldsm4(al[mt], sbAl + roff);
            }
            uint32_t bh[NT][2], bl[NT][2];
#pragma unroll
            for (int g = 0; g < NT / 2; g++) {
                uint32_t roff = (uint32_t)(wc * 64 + g * 16 + (lane & 15)) * (RS * 2) + koff;
                uint32_t r[4];
                ldsm4(r, sbWh + roff);
                bh[2 * g][0] = r[0]; bh[2 * g][1] = r[2];
                bh[2 * g + 1][0] = r[1]; bh[2 * g + 1][1] = r[3];
                ldsm4(r, sbWl + roff);
                bl[2 * g][0] = r[0]; bl[2 * g][1] = r[2];
                bl[2 * g + 1][0] = r[1]; bl[2 * g + 1][1] = r[3];
            }
#pragma unroll
            for (int mt = 0; mt < 2; mt++)
#pragma unroll
                for (int nt = 0; nt < NT; nt++) {
                    mma16816(acc[mt][nt], ah[mt], bh[nt]);
                    mma16816(acc[mt][nt], al[mt], bh[nt]);
                    mma16816(acc[mt][nt], ah[mt], bl[nt]);
                }
        }
        __syncthreads();
    }

#pragma unroll
    for (int nt = 0; nt < NT; nt++) {
        int col = wc * 64 + nt * 8 + (lane & 3) * 2;
        float2 bb = *reinterpret_cast<const float2*>(bias + col);
        float s0 = 0.f, s1 = 0.f, q0 = 0.f, q1 = 0.f;
#pragma unroll
        for (int mt = 0; mt < 2; mt++) {
            int r0 = rowBase + wr * 32 + mt * 16 + (lane >> 2);
            float v0 = acc[mt][nt][0] + bb.x, v1 = acc[mt][nt][1] + bb.y;
            float v2 = acc[mt][nt][2] + bb.x, v3 = acc[mt][nt][3] + bb.y;
            if (r0 < N_NODES) {
                *reinterpret_cast<float2*>(out + (size_t)r0 * 128 + col) = make_float2(v0, v1);
                s0 += v0; s1 += v1; q0 += v0 * v0; q1 += v1 * v1;
            }
            if (r0 + 8 < N_NODES) {
                *reinterpret_cast<float2*>(out + (size_t)(r0 + 8) * 128 + col) = make_float2(v2, v3);
                s0 += v2; s1 += v3; q0 += v2 * v2; q1 += v3 * v3;
            }
        }
#pragma unroll
        for (int off = 4; off < 32; off <<= 1) {
            s0 += __shfl_down_sync(0xffffffffu, s0, off);
            s1 += __shfl_down_sync(0xffffffffu, s1, off);
            q0 += __shfl_down_sync(0xffffffffu, q0, off);
            q1 += __shfl_down_sync(0xffffffffu, q1, off);
        }
        if ((lane >> 2) == 0) {
            atomicAdd(&ssum[col], s0); atomicAdd(&ssum[col + 1], s1);
            atomicAdd(&ssq[col], q0);  atomicAdd(&ssq[col + 1], q1);
        }
    }
    __syncthreads();
    if (tid < BN) {
        atomicAdd(&stSum[tid], ssum[tid]);
        atomicAdd(&stSq[tid], ssq[tid]);
    }
}

// ---------------- layer-2 GEMM: [z|s] = relu(bn(h1)) @ [Wl2|Wr2]^T ----------
// K=128, N=128; BN+ReLU+bf16 split fused into the A-load. Plain store.
__global__ __launch_bounds__(256)
void k_gemm_l2(const float* __restrict__ hin,
               const float* __restrict__ stSum, const float* __restrict__ stSq,
               const float* __restrict__ gamma, const float* __restrict__ beta,
               const __nv_bfloat16* __restrict__ Whi, const __nv_bfloat16* __restrict__ Wlo,
               float* __restrict__ zout) {
    constexpr int RS = 72;
    constexpr int NT = 8;
    extern __shared__ __nv_bfloat16 sm[];
    __nv_bfloat16* sAh = sm;
    __nv_bfloat16* sAl = sm + 128 * RS;
    __nv_bfloat16* sWh = sm + 2 * 128 * RS;
    __nv_bfloat16* sWl = sWh + 128 * RS;

    __shared__ float ssc[128], ssh[128];

    const int tid = threadIdx.x;
    const int lane = tid & 31;
    const int warp = tid >> 5;
    const int wr = warp & 3;
    const int wc = warp >> 2;
    const int rowBase = blockIdx.x * 128;

    if (tid < 128) {
        float mu = __ldg(stSum + tid) / (float)N_NODES;
        float var = __ldg(stSq + tid) / (float)N_NODES - mu * mu;
        float sc = __ldg(gamma + tid) * rsqrtf(var + BN_EPS);
        ssc[tid] = sc;
        ssh[tid] = __ldg(beta + tid) - mu * sc;
    }
    __syncthreads();

    const uint32_t sbAh = smem_u32(sAh);
    const uint32_t sbAl = smem_u32(sAl);
    const uint32_t sbWh = smem_u32(sWh);
    const uint32_t sbWl = smem_u32(sWl);

    float acc[2][NT][4];
#pragma unroll
    for (int mt = 0; mt < 2; mt++)
#pragma unroll
        for (int nt = 0; nt < NT; nt++)
#pragma unroll
            for (int j = 0; j < 4; j++) acc[mt][nt][j] = 0.f;

    for (int stage = 0; stage < 2; stage++) {
#pragma unroll
        for (int t = 0; t < 4; t++) {
            int idx = tid + t * 256;
            int r = idx >> 3, c = idx & 7;       // 8 fp32 cols per thread
            int row = rowBase + r;
            int col0 = stage * 64 + c * 8;
            __nv_bfloat16 hb[8], lb[8];
            if (row < N_NODES) {
                float4 u0 = __ldg(reinterpret_cast<const float4*>(hin + (size_t)row * D + col0));
                float4 u1 = __ldg(reinterpret_cast<const float4*>(hin + (size_t)row * D + col0 + 4));
                float a[8] = {u0.x, u0.y, u0.z, u0.w, u1.x, u1.y, u1.z, u1.w};
#pragma unroll
                for (int j = 0; j < 8; j++) {
                    float bn = fmaxf(fmaf(a[j], ssc[col0 + j], ssh[col0 + j]), 0.f);
                    bf16split(bn, hb[j], lb[j]);
                }
            } else {
#pragma unroll
                for (int j = 0; j < 8; j++) { hb[j] = __float2bfloat16(0.f); lb[j] = hb[j]; }
            }
            *reinterpret_cast<uint4*>(sAh + r * RS + c * 8) = *reinterpret_cast<uint4*>(hb);
            *reinterpret_cast<uint4*>(sAl + r * RS + c * 8) = *reinterpret_cast<uint4*>(lb);
        }
#pragma unroll
        for (int t = 0; t < 4; t++) {
            int idx = tid + t * 256;
            int n = idx >> 3, c = idx & 7;
            uint4 vh = __ldg(reinterpret_cast<const uint4*>(Whi + (size_t)n * 128 + stage * 64) + c);
            uint4 vl = __ldg(reinterpret_cast<const uint4*>(Wlo + (size_t)n * 128 + stage * 64) + c);
            *reinterpret_cast<uint4*>(sWh + n * RS + c * 8) = vh;
            *reinterpret_cast<uint4*>(sWl + n * RS + c * 8) = vl;
        }
        __syncthreads();

#pragma unroll
        for (int ks = 0; ks < 4; ks++) {
            const uint32_t koff = (uint32_t)(ks * 16 + (lane >> 4) * 8) * 2;
            uint32_t ah[2][4], al[2][4];
#pragma unroll
            for (int mt = 0; mt < 2; mt++) {
                uint32_t roff = (uint32_t)(wr * 32 + mt * 16 + (lane & 15)) * (RS * 2) + koff;
                ldsm4(ah[mt], sbAh + roff);
                ldsm4(al[mt], sbAl + roff);
            }
            uint32_t bh[NT][2], bl[NT][2];
#pragma unroll
            for (int g = 0; g < NT / 2; g++) {
                uint32_t roff = (uint32_t)(wc * 64 + g * 16 + (lane & 15)) * (RS * 2) + koff;
                uint32_t r[4];
                ldsm4(r, sbWh + roff);
                bh[2 * g][0] = r[0]; bh[2 * g][1] = r[2];
                bh[2 * g + 1][0] = r[1]; bh[2 * g + 1][1] = r[3];
                ldsm4(r, sbWl + roff);
                bl[2 * g][0] = r[0]; bl[2 * g][1] = r[2];
                bl[2 * g + 1][0] = r[1]; bl[2 * g + 1][1] = r[3];
            }
#pragma unroll
            for (int mt = 0; mt < 2; mt++)
#pragma unroll
                for (int nt = 0; nt < NT; nt++) {
                    mma16816(acc[mt][nt], ah[mt], bh[nt]);
                    mma16816(acc[mt][nt], al[mt], bh[nt]);
                    mma16816(acc[mt][nt], ah[mt], bl[nt]);
                }
        }
        __syncthreads();
    }

#pragma unroll
    for (int nt = 0; nt < NT; nt++) {
        int col = wc * 64 + nt * 8 + (lane & 3) * 2;
#pragma unroll
        for (int mt = 0; mt < 2; mt++) {
            int r0 = rowBase + wr * 32 + mt * 16 + (lane >> 2);
            if (r0 < N_NODES)
                *reinterpret_cast<float2*>(zout + (size_t)r0 * 128 + col) =
                    make_float2(acc[mt][nt][0], acc[mt][nt][1]);
            if (r0 + 8 < N_NODES)
                *reinterpret_cast<float2*>(zout + (size_t)(r0 + 8) * 128 + col) =
                    make_float2(acc[mt][nt][2], acc[mt][nt][3]);
        }
    }
}

// ---------------- final: out = log_softmax(mean(z[src]) + s + b2) -----------
// zs rows: [z (cols 0..63) | s (cols 64..127)]; warp per node, float2 per lane.
__global__ __launch_bounds__(256)
void k_final(const float* __restrict__ zs, const int* __restrict__ csr,
             const int* __restrict__ row_ptr, const float* __restrict__ b2,
             float* __restrict__ out) {
    int w = (blockIdx.x * blockDim.x + threadIdx.x) >> 5;
    if (w >= N_NODES) return;
    int lane = threadIdx.x & 31;
    int beg = __ldg(row_ptr + w);
    int end = __ldg(row_ptr + w + 1);
    float2 a0 = make_float2(0.f, 0.f), a1 = make_float2(0.f, 0.f);
    int i = beg;
    for (; i + 1 < end; i += 2) {
        int s0 = __ldg(csr + i);
        int s1 = __ldg(csr + i + 1);
        float2 v0 = __ldg(reinterpret_cast<const float2*>(zs + (size_t)s0 * 128) + lane);
        float2 v1 = __ldg(reinterpret_cast<const float2*>(zs + (size_t)s1 * 128) + lane);
        a0.x += v0.x; a0.y += v0.y;
        a1.x += v1.x; a1.y += v1.y;
    }
    if (i < end) {
        int s0 = __ldg(csr + i);
        float2 v0 = __ldg(reinterpret_cast<const float2*>(zs + (size_t)s0 * 128) + lane);
        a0.x += v0.x; a0.y += v0.y;
    }
    float inv = 1.f / (float)max(end - beg, 1);
    float2 sv = __ldg(reinterpret_cast<const float2*>(zs + (size_t)w * 128 + 64) + lane);
    float2 bb = __ldg(reinterpret_cast<const float2*>(b2) + lane);
    float v0 = (a0.x + a1.x) * inv + sv.x + bb.x;
    float v1 = (a0.y + a1.y) * inv + sv.y + bb.y;
    float m = fmaxf(v0, v1);
#pragma unroll
    for (int o = 16; o > 0; o >>= 1) m = fmaxf(m, __shfl_xor_sync(0xffffffffu, m, o));
    float e = expf(v0 - m) + expf(v1 - m);
#pragma unroll
    for (int o = 16; o > 0; o >>= 1) e += __shfl_xor_sync(0xffffffffu, e, o);
    float l = m + logf(e);
    *(reinterpret_cast<float2*>(out + (size_t)w * D_OUT) + lane) = make_float2(v0 - l, v1 - l);
}

// ---------------- launch ----------------------------------------------------
extern "C" void kernel_launch(void* const* d_in, const int* in_sizes, int n_in,
                              void* d_out, int out_size) {
    const float* x   = (const float*)d_in[0];
    const int* ei    = (const int*)d_in[1];
    const float* Wl0 = (const float*)d_in[2];
    const float* Wr0 = (const float*)d_in[3];
    const float* b0  = (const float*)d_in[4];
    const float* g0  = (const float*)d_in[5];
    const float* be0 = (const float*)d_in[6];
    const float* Wl1 = (const float*)d_in[7];
    const float* Wr1 = (const float*)d_in[8];
    const float* b1  = (const float*)d_in[9];
    const float* g1  = (const float*)d_in[10];
    const float* be1 = (const float*)d_in[11];
    const float* Wl2 = (const float*)d_in[12];
    const float* Wr2 = (const float*)d_in[13];
    const float* b2  = (const float*)d_in[14];
    float* out = (float*)d_out;

    const int E = in_sizes[1] / 2;
    const int* src = ei;
    const int* dst = ei + E;

    float *h0, *h1, *sum0, *sq0, *sum1, *sq1;
    __nv_bfloat16 *Ahi, *Alo, *Whi, *Wlo;
    int *cnti, *rowptr, *rank, *csr;
    cudaGetSymbolAddress((void**)&h0, g_h0);
    cudaGetSymbolAddress((void**)&h1, g_h1);
    cudaGetSymbolAddress((void**)&Ahi, g_Ahi);
    cudaGetSymbolAddress((void**)&Alo, g_Alo);
    cudaGetSymbolAddress((void**)&Whi, g_Whi);
    cudaGetSymbolAddress((void**)&Wlo, g_Wlo);
    cudaGetSymbolAddress((void**)&cnti, g_cnti);
    cudaGetSymbolAddress((void**)&rowptr, g_rowptr);
    cudaGetSymbolAddress((void**)&rank, g_rank);
    cudaGetSymbolAddress((void**)&csr, g_csr);
    cudaGetSymbolAddress((void**)&sum0, g_sum0);
    cudaGetSymbolAddress((void**)&sq0, g_sq0);
    cudaGetSymbolAddress((void**)&sum1, g_sum1);
    cudaGetSymbolAddress((void**)&sq1, g_sq1);

    constexpr int RS = 72;
    const int SMEM = (2 * 128 + 2 * 128) * RS * 2;  // 73728
    cudaFuncSetAttribute(k_mma_gemm, cudaFuncAttributeMaxDynamicSharedMemorySize, SMEM);
    cudaFuncSetAttribute(k_gemm_l2, cudaFuncAttributeMaxDynamicSharedMemorySize, SMEM);

    const int aggBlocks  = (N_NODES * 32 + 255) / 256;
    const int gemmBlocks = (N_NODES + 127) / 128;

    __nv_bfloat16* W0h = Whi;               __nv_bfloat16* W0l = Wlo;
    __nv_bfloat16* W1h = Whi + 128 * 256;   __nv_bfloat16* W1l = Wlo + 128 * 256;
    __nv_bfloat16* W2h = Whi + 256 * 256;   __nv_bfloat16* W2l = Wlo + 256 * 256;

    // ---- prep: weights + CSR ----
    k_prep<<<512, 256>>>(dst, E, cnti, rank, Wl0, Wr0, Wl1, Wr1, Wl2, Wr2, Whi, Wlo);
    k_scan<<<1, 1024>>>(cnti, rowptr);
    k_fill<<<512, 256>>>(src, dst, E, rank, rowptr, csr);

    // ---- layer 0 ----
    k_aggregate<false><<<aggBlocks, 256>>>(x, csr, rowptr, Ahi, Alo,
                                           nullptr, nullptr, nullptr, nullptr, sum0, sq0);
    k_mma_gemm<<<gemmBlocks, 256, SMEM>>>(Ahi, Alo, W0h, W0l, b0, h0, sum0, sq0);

    // ---- layer 1 (BN0+ReLU fused into aggregation) ----
    k_aggregate<true><<<aggBlocks, 256>>>(h0, csr, rowptr, Ahi, Alo,
                                          sum0, sq0, g0, be0, sum1, sq1);
    k_mma_gemm<<<gemmBlocks, 256, SMEM>>>(Ahi, Alo, W1h, W1l, b1, h1, sum1, sq1);

    // ---- layer 2 (commuted: GEMM first with BN1 inline, then 64-wide gather) ----
    k_gemm_l2<<<gemmBlocks, 256, SMEM>>>(h1, sum1, sq1, g1, be1, W2h, W2l, h0);
    k_final<<<aggBlocks, 256>>>(h0, csr, rowptr, b2, out);
}